// round 12
// baseline (speedup 1.0000x reference)
#include <cuda_runtime.h>
#include <cuda_bf16.h>
#include <cuda_fp16.h>
#include <cstdint>

#define NN 100000
#define NE 1600000
#define NEP 500000

// ---------------- scratch (device globals) ------------------------------------
__device__ int   g_deg[NN];
__device__ int   g_rowptr[NN + 1];
__device__ int   g_fill[NN];
__device__ float g_inv[NN];
__device__ int   g_col[NE];
__device__ int   g_bsum[128];
__device__ __nv_bfloat16 g_Zl[(size_t)NN * 128]; // x @ W_l0  (bf16 — gathered 16x)
__device__ float g_Zr[(size_t)NN * 128];          // x @ W_r0  (fp32 — read once)
__device__ __nv_bfloat16 g_hhi[(size_t)NN * 128]; // layer-0 output hi
__device__ __nv_bfloat16 g_hlo[(size_t)NN * 128]; // layer-0 output lo
__device__ __nv_bfloat16 g_Y1l[(size_t)NN * 64];  // h @ W_l1 (bf16 — gathered 16x)
__device__ float g_Y1r[(size_t)NN * 64];          // h @ W_r1 (fp32 — read once)
__device__ __half g_h2[(size_t)NN * 64];          // layer-1 output (fp16, 128B rows)
// B in per-lane mma-fragment layout: idx = ((m*8+ks)*16 + n8)*32 + lane
__device__ uint2 g_Bfh[3 * 4096];
__device__ uint2 g_Bfl[3 * 4096];

// ---------------- helpers -------------------------------------------------------
static __device__ __forceinline__ uint32_t smem_u32(const void* p) {
    uint32_t a;
    asm("{ .reg .u64 t; cvta.to.shared.u64 t, %1; cvt.u32.u64 %0, t; }" : "=r"(a) : "l"(p));
    return a;
}

static __device__ __forceinline__ void ldm_x4(uint32_t r[4], uint32_t addr) {
    asm volatile("ldmatrix.sync.aligned.m8n8.x4.shared.b16 {%0,%1,%2,%3}, [%4];"
        : "=r"(r[0]), "=r"(r[1]), "=r"(r[2]), "=r"(r[3]) : "r"(addr));
}

static __device__ __forceinline__ void mma16816(float c[4], const uint32_t a[4],
                                                const uint32_t b0, const uint32_t b1) {
    asm volatile("mma.sync.aligned.m16n8k16.row.col.f32.bf16.bf16.f32 "
        "{%0,%1,%2,%3}, {%4,%5,%6,%7}, {%8,%9}, {%0,%1,%2,%3};"
        : "+f"(c[0]), "+f"(c[1]), "+f"(c[2]), "+f"(c[3])
        : "r"(a[0]), "r"(a[1]), "r"(a[2]), "r"(a[3]), "r"(b0), "r"(b1));
}

// pack two fp32 into bf16-hi pair and bf16-lo (residual) pair
static __device__ __forceinline__ void cvt2(float a, float b, uint32_t& hi, uint32_t& lo) {
    __nv_bfloat16 ha = __float2bfloat16(a), hb = __float2bfloat16(b);
    hi = (uint32_t)__bfloat16_as_ushort(ha) | ((uint32_t)__bfloat16_as_ushort(hb) << 16);
    __nv_bfloat16 la = __float2bfloat16(a - __bfloat162float(ha));
    __nv_bfloat16 lb = __float2bfloat16(b - __bfloat162float(hb));
    lo = (uint32_t)__bfloat16_as_ushort(la) | ((uint32_t)__bfloat16_as_ushort(lb) << 16);
}

static __device__ __forceinline__ uint32_t packbf2(float a, float b) {
    __nv_bfloat162 p = __float22bfloat162_rn(make_float2(a, b));
    return *reinterpret_cast<uint32_t*>(&p);
}

static __device__ __forceinline__ void addbf2x2(float4& acc, uint2 v) {
    float2 f01 = __bfloat1622float2(*reinterpret_cast<const __nv_bfloat162*>(&v.x));
    float2 f23 = __bfloat1622float2(*reinterpret_cast<const __nv_bfloat162*>(&v.y));
    acc.x += f01.x; acc.y += f01.y; acc.z += f23.x; acc.w += f23.y;
}

// ---------------- CSR build ---------------------------------------------------
__global__ void k_count(const int* __restrict__ ei) {
    int e = blockIdx.x * blockDim.x + threadIdx.x;
    if (e < NE) atomicAdd(&g_deg[ei[NE + e]], 1);
}

__global__ void k_scan1() {
    int t = threadIdx.x, b = blockIdx.x;
    int i4 = b * 256 + t;
    int s = 0;
    if (i4 < NN / 4) {
        int4 d = ((const int4*)g_deg)[i4];
        s = d.x + d.y + d.z + d.w;
    }
    for (int o = 16; o; o >>= 1) s += __shfl_xor_sync(0xffffffffu, s, o);
    __shared__ int ws[8];
    if ((t & 31) == 0) ws[t >> 5] = s;
    __syncthreads();
    if (t == 0) {
        int tot = 0;
#pragma unroll
        for (int w = 0; w < 8; w++) tot += ws[w];
        g_bsum[b] = tot;
    }
}

__global__ void k_scan2(int nb) {
    __shared__ int s[128];
    int t = threadIdx.x;
    int v = (t < nb) ? g_bsum[t] : 0;
    s[t] = v;
    __syncthreads();
#pragma unroll
    for (int o = 1; o < 128; o <<= 1) {
        int u = (t >= o) ? s[t - o] : 0;
        __syncthreads();
        s[t] += u;
        __syncthreads();
    }
    if (t < nb) g_bsum[t] = s[t] - v;   // exclusive
    if (t == 0) g_rowptr[NN] = NE;
}

__global__ void k_scan3() {
    int t = threadIdx.x, b = blockIdx.x;
    int lane = t & 31, wid = t >> 5;
    int i4 = b * 256 + t;
    int4 d = make_int4(0, 0, 0, 0);
    bool act = (i4 < NN / 4);
    if (act) d = ((const int4*)g_deg)[i4];
    int e0 = 0, e1 = d.x, e2 = d.x + d.y, e3 = d.x + d.y + d.z;
    int tsum = e3 + d.w;
    int v = tsum;
#pragma unroll
    for (int o = 1; o < 32; o <<= 1) {
        int u = __shfl_up_sync(0xffffffffu, v, o);
        if (lane >= o) v += u;
    }
    __shared__ int wsum[8], woff[8];
    if (lane == 31) wsum[wid] = v;
    __syncthreads();
    if (t == 0) {
        int r = 0;
#pragma unroll
        for (int w = 0; w < 8; w++) { int tmp = wsum[w]; woff[w] = r; r += tmp; }
    }
    __syncthreads();
    if (act) {
        int base = g_bsum[b] + woff[wid] + (v - tsum);
        int i = i4 * 4;
        g_rowptr[i + 0] = base + e0;  g_fill[i + 0] = base + e0;
        g_rowptr[i + 1] = base + e1;  g_fill[i + 1] = base + e1;
        g_rowptr[i + 2] = base + e2;  g_fill[i + 2] = base + e2;
        g_rowptr[i + 3] = base + e3;  g_fill[i + 3] = base + e3;
        g_inv[i + 0] = 1.0f / (float)max(d.x, 1);
        g_inv[i + 1] = 1.0f / (float)max(d.y, 1);
        g_inv[i + 2] = 1.0f / (float)max(d.z, 1);
        g_inv[i + 3] = 1.0f / (float)max(d.w, 1);
    }
}

__global__ void k_scatter(const int* __restrict__ ei) {
    int e = blockIdx.x * blockDim.x + threadIdx.x;
    if (e < NE) {
        int dst = ei[NE + e];
        int p = atomicAdd(&g_fill[dst], 1);
        g_col[p] = ei[e];
    }
}

// ---------------- weight -> bf16 hi/lo mma-fragment layout ---------------------
// m=0: Wl0^T, m=1: Wr0^T, m=2: [Wl1|Wr1]^T
__global__ void k_cvt_w(const float* __restrict__ Wl0, const float* __restrict__ Wr0,
                        const float* __restrict__ Wl1, const float* __restrict__ Wr1) {
    int idx = blockIdx.x * blockDim.x + threadIdx.x;
    if (idx >= 3 * 4096) return;
    int lane = idx & 31;
    int n8   = (idx >> 5) & 15;
    int ks   = (idx >> 9) & 7;
    int m    = idx >> 12;
    int n  = n8 * 8 + (lane >> 2);
    int k0 = ks * 16 + (lane & 3) * 2;
    auto w = [&](int k) -> float {
        if (m == 0) return Wl0[k * 128 + n];
        if (m == 1) return Wr0[k * 128 + n];
        return (n < 64) ? Wl1[k * 64 + n] : Wr1[k * 64 + (n - 64)];
    };
    uint32_t h0, l0, h1, l1;
    cvt2(w(k0),     w(k0 + 1), h0, l0);
    cvt2(w(k0 + 8), w(k0 + 9), h1, l1);
    g_Bfh[idx] = make_uint2(h0, h1);
    g_Bfl[idx] = make_uint2(l0, l1);
}

// ---------------- HMMA GEMM: C[128 x 128] = A[128 x 128] @ B^T ----------------
// Compensated bf16x2: C = Ahi.Bhi + Ahi.Blo + Alo.Bhi (fp32 accum).
// OUTMODE: 0 = fp32 [M,128]; 1 = bf16 [M,128]; 2 = split bf16 [M,64] + fp32 [M,64]
#define LDAB 136
#define TILE_B (128 * LDAB * 2)          // 34816 bytes per tile
#define SA_HI 0
#define SA_LO TILE_B
#define SMEM_MMA (2 * TILE_B)            // 69632 bytes

template <int CVT, int OUTMODE>
__global__ __launch_bounds__(256, 2)
void k_mma(const void* __restrict__ Aany, const __nv_bfloat16* __restrict__ AloG,
           const uint2* __restrict__ Bfh, const uint2* __restrict__ Bfl,
           void* __restrict__ Cv, void* __restrict__ Cv2, int M) {
    extern __shared__ char smem[];
    const uint32_t sb = smem_u32(smem);
    const int tid = threadIdx.x, wid = tid >> 5, lane = tid & 31;
    const int rowBase = blockIdx.x * 128;

    // ---- stage A (fp32 -> bf16 hi/lo when CVT, else copy prepacked) ----
#pragma unroll
    for (int i = 0; i < 8; i++) {
        int f = tid + i * 256;                 // 8-element chunk id, [0,2048)
        int r = f >> 4, c16 = f & 15;
        uint32_t off = (uint32_t)r * (LDAB * 2) + c16 * 16;
        int gr = rowBase + r;
        if (CVT) {
            float4 v0 = make_float4(0.f, 0.f, 0.f, 0.f), v1 = v0;
            if (gr < M) {
                const float* ap = (const float*)Aany + (size_t)gr * 128 + c16 * 8;
                v0 = *(const float4*)ap;
                v1 = *(const float4*)(ap + 4);
            }
            uint4 hi, lo;
            cvt2(v0.x, v0.y, hi.x, lo.x);
            cvt2(v0.z, v0.w, hi.y, lo.y);
            cvt2(v1.x, v1.y, hi.z, lo.z);
            cvt2(v1.z, v1.w, hi.w, lo.w);
            *(uint4*)(smem + SA_HI + off) = hi;
            *(uint4*)(smem + SA_LO + off) = lo;
        } else {
            uint4 vh = make_uint4(0, 0, 0, 0), vl = vh;
            if (gr < M) {
                vh = *(const uint4*)((const __nv_bfloat16*)Aany + (size_t)gr * 128 + c16 * 8);
                vl = *(const uint4*)(AloG + (size_t)gr * 128 + c16 * 8);
            }
            *(uint4*)(smem + SA_HI + off) = vh;
            *(uint4*)(smem + SA_LO + off) = vl;
        }
    }
    __syncthreads();

    // warp tiling: 2 (m) x 4 (n); each warp does 64m x 32n
    const int wm = wid & 1, wn = wid >> 1;

    const int aRow = wm * 64 + (lane & 7) + ((lane >> 3) & 1) * 8;
    const int aCol = ((lane >> 4) & 1) * 8;
    uint32_t aOff[4];
#pragma unroll
    for (int mf = 0; mf < 4; mf++)
        aOff[mf] = sb + (uint32_t)(aRow + mf * 16) * (LDAB * 2) + (uint32_t)aCol * 2;

    float acc[4][4][4];
#pragma unroll
    for (int mf = 0; mf < 4; mf++)
#pragma unroll
        for (int nf = 0; nf < 4; nf++)
#pragma unroll
            for (int q = 0; q < 4; q++) acc[mf][nf][q] = 0.f;

#pragma unroll
    for (int ks = 0; ks < 8; ks++) {
        const uint32_t kb = ks * 32;       // 16 bf16 = 32 bytes
        const int fibase = (ks * 16 + wn * 4) * 32 + lane;
        uint2 bh[4], bl[4];
#pragma unroll
        for (int nf = 0; nf < 4; nf++) {
            bh[nf] = Bfh[fibase + nf * 32];
            bl[nf] = Bfl[fibase + nf * 32];
        }
        uint32_t a[4][4];
#pragma unroll
        for (int mf = 0; mf < 4; mf++) ldm_x4(a[mf], aOff[mf] + SA_HI + kb);
#pragma unroll
        for (int mf = 0; mf < 4; mf++)
#pragma unroll
            for (int nf = 0; nf < 4; nf++)
                mma16816(acc[mf][nf], a[mf], bh[nf].x, bh[nf].y);
#pragma unroll
        for (int mf = 0; mf < 4; mf++)
#pragma unroll
            for (int nf = 0; nf < 4; nf++)
                mma16816(acc[mf][nf], a[mf], bl[nf].x, bl[nf].y);
#pragma unroll
        for (int mf = 0; mf < 4; mf++) ldm_x4(a[mf], aOff[mf] + SA_LO + kb);
#pragma unroll
        for (int mf = 0; mf < 4; mf++)
#pragma unroll
            for (int nf = 0; nf < 4; nf++)
                mma16816(acc[mf][nf], a[mf], bh[nf].x, bh[nf].y);
    }

    // ---- epilogue ----
    const int quad = lane >> 2, pairc = (lane & 3) * 2;
#pragma unroll
    for (int mf = 0; mf < 4; mf++) {
        int r0 = rowBase + wm * 64 + mf * 16 + quad;
#pragma unroll
        for (int nf = 0; nf < 4; nf++) {
            int c0 = wn * 32 + nf * 8 + pairc;
            if (OUTMODE == 1) {
                __nv_bfloat16* Cb = (__nv_bfloat16*)Cv;
                if (r0 < M)
                    *(uint32_t*)(Cb + (size_t)r0 * 128 + c0) = packbf2(acc[mf][nf][0], acc[mf][nf][1]);
                if (r0 + 8 < M)
                    *(uint32_t*)(Cb + (size_t)(r0 + 8) * 128 + c0) = packbf2(acc[mf][nf][2], acc[mf][nf][3]);
            } else if (OUTMODE == 2) {
                if (c0 < 64) {   // left half -> bf16, ld 64
                    __nv_bfloat16* Cb = (__nv_bfloat16*)Cv;
                    if (r0 < M)
                        *(uint32_t*)(Cb + (size_t)r0 * 64 + c0) = packbf2(acc[mf][nf][0], acc[mf][nf][1]);
                    if (r0 + 8 < M)
                        *(uint32_t*)(Cb + (size_t)(r0 + 8) * 64 + c0) = packbf2(acc[mf][nf][2], acc[mf][nf][3]);
                } else {         // right half -> fp32, ld 64
                    float* C = (float*)Cv2;
                    int c1 = c0 - 64;
                    if (r0 < M)
                        *(float2*)(C + (size_t)r0 * 64 + c1) = make_float2(acc[mf][nf][0], acc[mf][nf][1]);
                    if (r0 + 8 < M)
                        *(float2*)(C + (size_t)(r0 + 8) * 64 + c1) = make_float2(acc[mf][nf][2], acc[mf][nf][3]);
                }
            } else {
                float* C = (float*)Cv;
                if (r0 < M)
                    *(float2*)(C + (size_t)r0 * 128 + c0) = make_float2(acc[mf][nf][0], acc[mf][nf][1]);
                if (r0 + 8 < M)
                    *(float2*)(C + (size_t)(r0 + 8) * 128 + c0) = make_float2(acc[mf][nf][2], acc[mf][nf][3]);
            }
        }
    }
}

// ---------------- aggregation epilogues (4-way MLP-batched gathers) ------------
// layer 0: h = relu( inv*sum_j bf16(Zl[j]) + Zr[i] + b0 ), emit bf16 hi/lo
__global__ void k_agg0(const float* __restrict__ b0) {
    int w = (blockIdx.x * blockDim.x + threadIdx.x) >> 5;
    int lane = threadIdx.x & 31;
    if (w >= NN) return;
    int s = g_rowptr[w], e = g_rowptr[w + 1];
    const uint2* Z = (const uint2*)g_Zl;      // 32 uint2 (256B) per row
    float4 a0 = make_float4(0.f, 0.f, 0.f, 0.f), a1 = a0, a2 = a0, a3 = a0;
    int p = s;
    for (; p + 4 <= e; p += 4) {
        int j0 = g_col[p], j1 = g_col[p + 1], j2 = g_col[p + 2], j3 = g_col[p + 3];
        uint2 v0 = Z[(size_t)j0 * 32 + lane];
        uint2 v1 = Z[(size_t)j1 * 32 + lane];
        uint2 v2 = Z[(size_t)j2 * 32 + lane];
        uint2 v3 = Z[(size_t)j3 * 32 + lane];
        addbf2x2(a0, v0);
        addbf2x2(a1, v1);
        addbf2x2(a2, v2);
        addbf2x2(a3, v3);
    }
    for (; p < e; p++) {
        int j = g_col[p];
        addbf2x2(a0, Z[(size_t)j * 32 + lane]);
    }
    a0.x += a1.x + a2.x + a3.x;
    a0.y += a1.y + a2.y + a3.y;
    a0.z += a1.z + a2.z + a3.z;
    a0.w += a1.w + a2.w + a3.w;
    float inv = g_inv[w];
    float4 r = ((const float4*)g_Zr)[(size_t)w * 32 + lane];
    float4 bb = ((const float4*)b0)[lane];
    float o0 = fmaxf(fmaf(a0.x, inv, r.x + bb.x), 0.f);
    float o1 = fmaxf(fmaf(a0.y, inv, r.y + bb.y), 0.f);
    float o2 = fmaxf(fmaf(a0.z, inv, r.z + bb.z), 0.f);
    float o3 = fmaxf(fmaf(a0.w, inv, r.w + bb.w), 0.f);
    uint32_t h01, l01, h23, l23;
    cvt2(o0, o1, h01, l01);
    cvt2(o2, o3, h23, l23);
    ((uint2*)g_hhi)[(size_t)w * 32 + lane] = make_uint2(h01, h23);
    ((uint2*)g_hlo)[(size_t)w * 32 + lane] = make_uint2(l01, l23);
}

// layer 1: h2 = inv*sum_j bf16(Y1l[j]) + Y1r[i] + b1 (fp32 accum, fp16 out)
__global__ void k_agg1(const float* __restrict__ b1) {
    int w = (blockIdx.x * blockDim.x + threadIdx.x) >> 5;
    int lane = threadIdx.x & 31;
    if (w >= NN) return;
    int s = g_rowptr[w], e = g_rowptr[w + 1];
    const uint32_t* Yl = (const uint32_t*)g_Y1l;   // 32 uint32 (128B) per row
    float2 a0 = make_float2(0.f, 0.f), a1 = a0, a2 = a0, a3 = a0;
    int p = s;
    for (; p + 4 <= e; p += 4) {
        int j0 = g_col[p], j1 = g_col[p + 1], j2 = g_col[p + 2], j3 = g_col[p + 3];
        uint32_t v0 = Yl[(size_t)j0 * 32 + lane];
        uint32_t v1 = Yl[(size_t)j1 * 32 + lane];
        uint32_t v2 = Yl[(size_t)j2 * 32 + lane];
        uint32_t v3 = Yl[(size_t)j3 * 32 + lane];
        float2 f0 = __bfloat1622float2(*reinterpret_cast<const __nv_bfloat162*>(&v0));
        float2 f1 = __bfloat1622float2(*reinterpret_cast<const __nv_bfloat162*>(&v1));
        float2 f2 = __bfloat1622float2(*reinterpret_cast<const __nv_bfloat162*>(&v2));
        float2 f3 = __bfloat1622float2(*reinterpret_cast<const __nv_bfloat162*>(&v3));
        a0.x += f0.x; a0.y += f0.y;
        a1.x += f1.x; a1.y += f1.y;
        a2.x += f2.x; a2.y += f2.y;
        a3.x += f3.x; a3.y += f3.y;
    }
    for (; p < e; p++) {
        int j = g_col[p];
        uint32_t v = Yl[(size_t)j * 32 + lane];
        float2 f = __bfloat1622float2(*reinterpret_cast<const __nv_bfloat162*>(&v));
        a0.x += f.x; a0.y += f.y;
    }
    a0.x += a1.x + a2.x + a3.x;
    a0.y += a1.y + a2.y + a3.y;
    float inv = g_inv[w];
    float2 r = ((const float2*)g_Y1r)[(size_t)w * 32 + lane];
    float2 bb = ((const float2*)b1)[lane];
    float2 o;
    o.x = fmaf(a0.x, inv, r.x + bb.x);
    o.y = fmaf(a0.y, inv, r.y + bb.y);
    __half2 oh = __float22half2_rn(o);
    ((uint32_t*)g_h2)[(size_t)w * 32 + lane] = *reinterpret_cast<uint32_t*>(&oh);
}

// ---------------- edge scoring: 4 edges/warp, 8 lanes/edge ----------------------
__global__ void k_score(const int* __restrict__ pe, const int* __restrict__ ne,
                        float* __restrict__ out) {
    int gw = (blockIdx.x * blockDim.x + threadIdx.x) >> 5;   // warp id
    int lane = threadIdx.x & 31;
    int g = lane >> 3, l8 = lane & 7;
    int e = gw * 4 + g;                 // edge id in [0, 2*NEP); warps never straddle
    if (e >= 2 * NEP) return;
    int a, b;
    if (e < NEP) { a = pe[e]; b = pe[NEP + e]; }
    else         { int q = e - NEP; a = ne[q]; b = ne[NEP + q]; }
    const uint4* H = (const uint4*)g_h2;    // row = 8 uint4 (64 halves)
    uint4 ua = H[(size_t)a * 8 + l8];
    uint4 ub = H[(size_t)b * 8 + l8];
    float s;
    {
        float2 a0 = __half22float2(*reinterpret_cast<const __half2*>(&ua.x));
        float2 b0 = __half22float2(*reinterpret_cast<const __half2*>(&ub.x));
        float2 a1 = __half22float2(*reinterpret_cast<const __half2*>(&ua.y));
        float2 b1 = __half22float2(*reinterpret_cast<const __half2*>(&ub.y));
        float2 a2 = __half22float2(*reinterpret_cast<const __half2*>(&ua.z));
        float2 b2 = __half22float2(*reinterpret_cast<const __half2*>(&ub.z));
        float2 a3 = __half22float2(*reinterpret_cast<const __half2*>(&ua.w));
        float2 b3 = __half22float2(*reinterpret_cast<const __half2*>(&ub.w));
        s = a0.x * b0.x;
        s = fmaf(a0.y, b0.y, s);
        s = fmaf(a1.x, b1.x, s);
        s = fmaf(a1.y, b1.y, s);
        s = fmaf(a2.x, b2.x, s);
        s = fmaf(a2.y, b2.y, s);
        s = fmaf(a3.x, b3.x, s);
        s = fmaf(a3.y, b3.y, s);
    }
    s += __shfl_xor_sync(0xffffffffu, s, 4);
    s += __shfl_xor_sync(0xffffffffu, s, 2);
    s += __shfl_xor_sync(0xffffffffu, s, 1);
    if (l8 == 0) out[e] = s;
}

// ---------------- launcher -----------------------------------------------------
extern "C" void kernel_launch(void* const* d_in, const int* in_sizes, int n_in,
                              void* d_out, int out_size) {
    const float* x   = (const float*)d_in[0];
    const int*   ei  = (const int*)d_in[1];
    const int*   pe  = (const int*)d_in[2];
    const int*   ne  = (const int*)d_in[3];
    const float* Wl0 = (const float*)d_in[4];
    const float* b0  = (const float*)d_in[5];
    const float* Wr0 = (const float*)d_in[6];
    const float* Wl1 = (const float*)d_in[7];
    const float* b1  = (const float*)d_in[8];
    const float* Wr1 = (const float*)d_in[9];
    float* out = (float*)d_out;

    static cudaStream_t s1 = nullptr, s2 = nullptr;
    static cudaEvent_t eF = nullptr, eW = nullptr, e1 = nullptr, e2 = nullptr;
    if (s1 == nullptr) {
        cudaStreamCreateWithFlags(&s1, cudaStreamNonBlocking);
        cudaStreamCreateWithFlags(&s2, cudaStreamNonBlocking);
        cudaEventCreateWithFlags(&eF, cudaEventDisableTiming);
        cudaEventCreateWithFlags(&eW, cudaEventDisableTiming);
        cudaEventCreateWithFlags(&e1, cudaEventDisableTiming);
        cudaEventCreateWithFlags(&e2, cudaEventDisableTiming);
        cudaFuncSetAttribute((const void*)k_mma<1, 1>, cudaFuncAttributeMaxDynamicSharedMemorySize, SMEM_MMA);
        cudaFuncSetAttribute((const void*)k_mma<1, 0>, cudaFuncAttributeMaxDynamicSharedMemorySize, SMEM_MMA);
        cudaFuncSetAttribute((const void*)k_mma<0, 2>, cudaFuncAttributeMaxDynamicSharedMemorySize, SMEM_MMA);
    }

    __nv_bfloat16 *pZl, *pHhi, *pHlo, *pY1l;
    float *pZr, *pY1r;
    uint2 *pBfh, *pBfl;
    int *pDeg;
    cudaGetSymbolAddress((void**)&pZl,  g_Zl);
    cudaGetSymbolAddress((void**)&pZr,  g_Zr);
    cudaGetSymbolAddress((void**)&pY1l, g_Y1l);
    cudaGetSymbolAddress((void**)&pY1r, g_Y1r);
    cudaGetSymbolAddress((void**)&pHhi, g_hhi);
    cudaGetSymbolAddress((void**)&pHlo, g_hlo);
    cudaGetSymbolAddress((void**)&pBfh, g_Bfh);
    cudaGetSymbolAddress((void**)&pBfl, g_Bfl);
    cudaGetSymbolAddress((void**)&pDeg, g_deg);

    const int NB = (NN + 1023) / 1024;   // 98
    const int GX = (NN + 127) / 128;     // 782

    // fork: s1/s2 branch off the main (captured) stream
    cudaEventRecord(eF, 0);
    cudaStreamWaitEvent(s1, eF, 0);

    // branch A (s1/s2): weights -> layer-0 GEMMs (Zl bf16-out, Zr fp32-out)
    k_cvt_w<<<48, 256, 0, s1>>>(Wl0, Wr0, Wl1, Wr1);
    cudaEventRecord(eW, s1);
    cudaStreamWaitEvent(s2, eW, 0);
    k_mma<1, 1><<<GX, 256, SMEM_MMA, s1>>>(x, nullptr, pBfh,        pBfl,        pZl, nullptr, NN);
    k_mma<1, 0><<<GX, 256, SMEM_MMA, s2>>>(x, nullptr, pBfh + 4096, pBfl + 4096, pZr, nullptr, NN);

    // branch B (main stream): CSR build
    cudaMemsetAsync(pDeg, 0, NN * sizeof(int), 0);
    k_count<<<(NE + 255) / 256, 256>>>(ei);
    k_scan1<<<NB, 256>>>();
    k_scan2<<<1, 128>>>(NB);
    k_scan3<<<NB, 256>>>();
    k_scatter<<<(NE + 255) / 256, 256>>>(ei);

    // join
    cudaEventRecord(e1, s1);
    cudaEventRecord(e2, s2);
    cudaStreamWaitEvent(0, e1, 0);
    cudaStreamWaitEvent(0, e2, 0);

    // layer 0 aggregate, layer 1 (split bf16/fp32 out), layer-1 aggregate, scores
    k_agg0<<<(NN * 32 + 255) / 256, 256>>>(b0);
    k_mma<0, 2><<<GX, 256, SMEM_MMA>>>(pHhi, pHlo, pBfh + 8192, pBfl + 8192, pY1l, pY1r, NN);
    k_agg1<<<(NN * 32 + 255) / 256, 256>>>(b1);
    // 4 edges per warp: 2*NEP/4 = 250K warps -> 31250 blocks of 256 threads
    k_score<<<(2 * NEP / 4 * 32) / 256, 256>>>(pe, ne, out);
}

// round 13
// speedup vs baseline: 1.0818x; 1.0818x over previous
#include <cuda_runtime.h>
#include <cuda_bf16.h>
#include <cuda_fp16.h>
#include <cstdint>

#define NN 100000
#define NE 1600000
#define NEP 500000

// ---------------- scratch (device globals) ------------------------------------
__device__ int   g_deg[NN];
__device__ int   g_rowptr[NN + 1];
__device__ int   g_fill[NN];
__device__ float g_inv[NN];
__device__ int   g_col[NE];
__device__ int   g_bsum[128];
__device__ __nv_bfloat16 g_Zl[(size_t)NN * 128]; // x @ W_l0  (bf16 — gathered 16x)
__device__ float g_Zr[(size_t)NN * 128];          // x @ W_r0  (fp32 — read once)
__device__ __nv_bfloat16 g_hhi[(size_t)NN * 128]; // layer-0 output hi
__device__ __nv_bfloat16 g_hlo[(size_t)NN * 128]; // layer-0 output lo
__device__ __nv_bfloat16 g_Y1l[(size_t)NN * 64];  // h @ W_l1 (bf16 — gathered 16x)
__device__ float g_Y1r[(size_t)NN * 64];          // h @ W_r1 (fp32 — read once)
__device__ __half g_h2[(size_t)NN * 64];          // layer-1 output (fp16, 128B rows)
// B in per-lane mma-fragment layout: idx = ((m*8+ks)*16 + n8)*32 + lane
__device__ uint2 g_Bfh[3 * 4096];
__device__ uint2 g_Bfl[3 * 4096];

// ---------------- helpers -------------------------------------------------------
static __device__ __forceinline__ uint32_t smem_u32(const void* p) {
    uint32_t a;
    asm("{ .reg .u64 t; cvta.to.shared.u64 t, %1; cvt.u32.u64 %0, t; }" : "=r"(a) : "l"(p));
    return a;
}

static __device__ __forceinline__ void ldm_x4(uint32_t r[4], uint32_t addr) {
    asm volatile("ldmatrix.sync.aligned.m8n8.x4.shared.b16 {%0,%1,%2,%3}, [%4];"
        : "=r"(r[0]), "=r"(r[1]), "=r"(r[2]), "=r"(r[3]) : "r"(addr));
}

static __device__ __forceinline__ void mma16816(float c[4], const uint32_t a[4],
                                                const uint32_t b0, const uint32_t b1) {
    asm volatile("mma.sync.aligned.m16n8k16.row.col.f32.bf16.bf16.f32 "
        "{%0,%1,%2,%3}, {%4,%5,%6,%7}, {%8,%9}, {%0,%1,%2,%3};"
        : "+f"(c[0]), "+f"(c[1]), "+f"(c[2]), "+f"(c[3])
        : "r"(a[0]), "r"(a[1]), "r"(a[2]), "r"(a[3]), "r"(b0), "r"(b1));
}

// pack two fp32 into bf16-hi pair and bf16-lo (residual) pair
static __device__ __forceinline__ void cvt2(float a, float b, uint32_t& hi, uint32_t& lo) {
    __nv_bfloat16 ha = __float2bfloat16(a), hb = __float2bfloat16(b);
    hi = (uint32_t)__bfloat16_as_ushort(ha) | ((uint32_t)__bfloat16_as_ushort(hb) << 16);
    __nv_bfloat16 la = __float2bfloat16(a - __bfloat162float(ha));
    __nv_bfloat16 lb = __float2bfloat16(b - __bfloat162float(hb));
    lo = (uint32_t)__bfloat16_as_ushort(la) | ((uint32_t)__bfloat16_as_ushort(lb) << 16);
}

static __device__ __forceinline__ uint32_t packbf2(float a, float b) {
    __nv_bfloat162 p = __float22bfloat162_rn(make_float2(a, b));
    return *reinterpret_cast<uint32_t*>(&p);
}

// ---------------- CSR build ---------------------------------------------------
__global__ void k_count(const int* __restrict__ ei) {
    int e = blockIdx.x * blockDim.x + threadIdx.x;
    if (e < NE) atomicAdd(&g_deg[ei[NE + e]], 1);
}

__global__ void k_scan1() {
    int t = threadIdx.x, b = blockIdx.x;
    int i4 = b * 256 + t;
    int s = 0;
    if (i4 < NN / 4) {
        int4 d = ((const int4*)g_deg)[i4];
        s = d.x + d.y + d.z + d.w;
    }
    for (int o = 16; o; o >>= 1) s += __shfl_xor_sync(0xffffffffu, s, o);
    __shared__ int ws[8];
    if ((t & 31) == 0) ws[t >> 5] = s;
    __syncthreads();
    if (t == 0) {
        int tot = 0;
#pragma unroll
        for (int w = 0; w < 8; w++) tot += ws[w];
        g_bsum[b] = tot;
    }
}

__global__ void k_scan2(int nb) {
    __shared__ int s[128];
    int t = threadIdx.x;
    int v = (t < nb) ? g_bsum[t] : 0;
    s[t] = v;
    __syncthreads();
#pragma unroll
    for (int o = 1; o < 128; o <<= 1) {
        int u = (t >= o) ? s[t - o] : 0;
        __syncthreads();
        s[t] += u;
        __syncthreads();
    }
    if (t < nb) g_bsum[t] = s[t] - v;   // exclusive
    if (t == 0) g_rowptr[NN] = NE;
}

__global__ void k_scan3() {
    int t = threadIdx.x, b = blockIdx.x;
    int lane = t & 31, wid = t >> 5;
    int i4 = b * 256 + t;
    int4 d = make_int4(0, 0, 0, 0);
    bool act = (i4 < NN / 4);
    if (act) d = ((const int4*)g_deg)[i4];
    int e0 = 0, e1 = d.x, e2 = d.x + d.y, e3 = d.x + d.y + d.z;
    int tsum = e3 + d.w;
    int v = tsum;
#pragma unroll
    for (int o = 1; o < 32; o <<= 1) {
        int u = __shfl_up_sync(0xffffffffu, v, o);
        if (lane >= o) v += u;
    }
    __shared__ int wsum[8], woff[8];
    if (lane == 31) wsum[wid] = v;
    __syncthreads();
    if (t == 0) {
        int r = 0;
#pragma unroll
        for (int w = 0; w < 8; w++) { int tmp = wsum[w]; woff[w] = r; r += tmp; }
    }
    __syncthreads();
    if (act) {
        int base = g_bsum[b] + woff[wid] + (v - tsum);
        int i = i4 * 4;
        g_rowptr[i + 0] = base + e0;  g_fill[i + 0] = base + e0;
        g_rowptr[i + 1] = base + e1;  g_fill[i + 1] = base + e1;
        g_rowptr[i + 2] = base + e2;  g_fill[i + 2] = base + e2;
        g_rowptr[i + 3] = base + e3;  g_fill[i + 3] = base + e3;
        g_inv[i + 0] = 1.0f / (float)max(d.x, 1);
        g_inv[i + 1] = 1.0f / (float)max(d.y, 1);
        g_inv[i + 2] = 1.0f / (float)max(d.z, 1);
        g_inv[i + 3] = 1.0f / (float)max(d.w, 1);
    }
}

__global__ void k_scatter(const int* __restrict__ ei) {
    int e = blockIdx.x * blockDim.x + threadIdx.x;
    if (e < NE) {
        int dst = ei[NE + e];
        int p = atomicAdd(&g_fill[dst], 1);
        g_col[p] = ei[e];
    }
}

// ---------------- weight -> bf16 hi/lo mma-fragment layout ---------------------
// m=0: Wl0^T, m=1: Wr0^T, m=2: [Wl1|Wr1]^T
__global__ void k_cvt_w(const float* __restrict__ Wl0, const float* __restrict__ Wr0,
                        const float* __restrict__ Wl1, const float* __restrict__ Wr1) {
    int idx = blockIdx.x * blockDim.x + threadIdx.x;
    if (idx >= 3 * 4096) return;
    int lane = idx & 31;
    int n8   = (idx >> 5) & 15;
    int ks   = (idx >> 9) & 7;
    int m    = idx >> 12;
    int n  = n8 * 8 + (lane >> 2);
    int k0 = ks * 16 + (lane & 3) * 2;
    auto w = [&](int k) -> float {
        if (m == 0) return Wl0[k * 128 + n];
        if (m == 1) return Wr0[k * 128 + n];
        return (n < 64) ? Wl1[k * 64 + n] : Wr1[k * 64 + (n - 64)];
    };
    uint32_t h0, l0, h1, l1;
    cvt2(w(k0),     w(k0 + 1), h0, l0);
    cvt2(w(k0 + 8), w(k0 + 9), h1, l1);
    g_Bfh[idx] = make_uint2(h0, h1);
    g_Bfl[idx] = make_uint2(l0, l1);
}

// ---------------- HMMA GEMM core -----------------------------------------------
// Compensated bf16x2: acc += Ahi.Bhi + Ahi.Blo + Alo.Bhi (fp32 accum).
#define LDAB 136
#define TILE_B (128 * LDAB * 2)          // 34816 bytes per tile
#define SA_HI 0
#define SA_LO TILE_B
#define SMEM_MMA (2 * TILE_B)            // 69632 bytes

static __device__ __forceinline__ void gemm_main(float (&acc)[4][4][4],
                                                 const uint32_t aOff[4],
                                                 const uint2* __restrict__ Bfh,
                                                 const uint2* __restrict__ Bfl,
                                                 int wn, int lane) {
#pragma unroll
    for (int mf = 0; mf < 4; mf++)
#pragma unroll
        for (int nf = 0; nf < 4; nf++)
#pragma unroll
            for (int q = 0; q < 4; q++) acc[mf][nf][q] = 0.f;
#pragma unroll
    for (int ks = 0; ks < 8; ks++) {
        const uint32_t kb = ks * 32;       // 16 bf16 = 32 bytes
        const int fibase = (ks * 16 + wn * 4) * 32 + lane;
        uint2 bh[4], bl[4];
#pragma unroll
        for (int nf = 0; nf < 4; nf++) {
            bh[nf] = Bfh[fibase + nf * 32];
            bl[nf] = Bfl[fibase + nf * 32];
        }
        uint32_t a[4][4];
#pragma unroll
        for (int mf = 0; mf < 4; mf++) ldm_x4(a[mf], aOff[mf] + SA_HI + kb);
#pragma unroll
        for (int mf = 0; mf < 4; mf++)
#pragma unroll
            for (int nf = 0; nf < 4; nf++)
                mma16816(acc[mf][nf], a[mf], bh[nf].x, bh[nf].y);
#pragma unroll
        for (int mf = 0; mf < 4; mf++)
#pragma unroll
            for (int nf = 0; nf < 4; nf++)
                mma16816(acc[mf][nf], a[mf], bl[nf].x, bl[nf].y);
#pragma unroll
        for (int mf = 0; mf < 4; mf++) ldm_x4(a[mf], aOff[mf] + SA_LO + kb);
#pragma unroll
        for (int mf = 0; mf < 4; mf++)
#pragma unroll
            for (int nf = 0; nf < 4; nf++)
                mma16816(acc[mf][nf], a[mf], bh[nf].x, bh[nf].y);
    }
}

// merged layer-0 GEMM: stage/convert A ONCE, two MMA passes.
// pass 1: B=Wl0^T -> Zl (bf16, ld 128). pass 2: B=Wr0^T -> Zr (fp32, ld 128).
__global__ __launch_bounds__(256, 2)
void k_mma0dual(const float* __restrict__ A,
                const uint2* __restrict__ Bfh0, const uint2* __restrict__ Bfl0,
                const uint2* __restrict__ Bfh1, const uint2* __restrict__ Bfl1,
                __nv_bfloat16* __restrict__ Cl, float* __restrict__ Cr, int M) {
    extern __shared__ char smem[];
    const uint32_t sb = smem_u32(smem);
    const int tid = threadIdx.x, wid = tid >> 5, lane = tid & 31;
    const int rowBase = blockIdx.x * 128;

    // ---- stage A: fp32 -> bf16 hi/lo (once) ----
#pragma unroll
    for (int i = 0; i < 8; i++) {
        int f = tid + i * 256;
        int r = f >> 4, c16 = f & 15;
        uint32_t off = (uint32_t)r * (LDAB * 2) + c16 * 16;
        int gr = rowBase + r;
        float4 v0 = make_float4(0.f, 0.f, 0.f, 0.f), v1 = v0;
        if (gr < M) {
            const float* ap = A + (size_t)gr * 128 + c16 * 8;
            v0 = *(const float4*)ap;
            v1 = *(const float4*)(ap + 4);
        }
        uint4 hi, lo;
        cvt2(v0.x, v0.y, hi.x, lo.x);
        cvt2(v0.z, v0.w, hi.y, lo.y);
        cvt2(v1.x, v1.y, hi.z, lo.z);
        cvt2(v1.z, v1.w, hi.w, lo.w);
        *(uint4*)(smem + SA_HI + off) = hi;
        *(uint4*)(smem + SA_LO + off) = lo;
    }
    __syncthreads();

    const int wm = wid & 1, wn = wid >> 1;
    const int aRow = wm * 64 + (lane & 7) + ((lane >> 3) & 1) * 8;
    const int aCol = ((lane >> 4) & 1) * 8;
    uint32_t aOff[4];
#pragma unroll
    for (int mf = 0; mf < 4; mf++)
        aOff[mf] = sb + (uint32_t)(aRow + mf * 16) * (LDAB * 2) + (uint32_t)aCol * 2;

    const int quad = lane >> 2, pairc = (lane & 3) * 2;
    float acc[4][4][4];

    // ---- pass 1: Zl (bf16 out) ----
    gemm_main(acc, aOff, Bfh0, Bfl0, wn, lane);
#pragma unroll
    for (int mf = 0; mf < 4; mf++) {
        int r0 = rowBase + wm * 64 + mf * 16 + quad;
#pragma unroll
        for (int nf = 0; nf < 4; nf++) {
            int c0 = wn * 32 + nf * 8 + pairc;
            if (r0 < M)
                *(uint32_t*)(Cl + (size_t)r0 * 128 + c0) = packbf2(acc[mf][nf][0], acc[mf][nf][1]);
            if (r0 + 8 < M)
                *(uint32_t*)(Cl + (size_t)(r0 + 8) * 128 + c0) = packbf2(acc[mf][nf][2], acc[mf][nf][3]);
        }
    }

    // ---- pass 2: Zr (fp32 out) ----
    gemm_main(acc, aOff, Bfh1, Bfl1, wn, lane);
#pragma unroll
    for (int mf = 0; mf < 4; mf++) {
        int r0 = rowBase + wm * 64 + mf * 16 + quad;
#pragma unroll
        for (int nf = 0; nf < 4; nf++) {
            int c0 = wn * 32 + nf * 8 + pairc;
            if (r0 < M)
                *(float2*)(Cr + (size_t)r0 * 128 + c0) = make_float2(acc[mf][nf][0], acc[mf][nf][1]);
            if (r0 + 8 < M)
                *(float2*)(Cr + (size_t)(r0 + 8) * 128 + c0) = make_float2(acc[mf][nf][2], acc[mf][nf][3]);
        }
    }
}

// layer-1 GEMM: A prepacked bf16 hi/lo -> split out (bf16 Y1l, fp32 Y1r)
__global__ __launch_bounds__(256, 2)
void k_mma1(const __nv_bfloat16* __restrict__ AhiG, const __nv_bfloat16* __restrict__ AloG,
            const uint2* __restrict__ Bfh, const uint2* __restrict__ Bfl,
            __nv_bfloat16* __restrict__ Cl, float* __restrict__ Cr, int M) {
    extern __shared__ char smem[];
    const uint32_t sb = smem_u32(smem);
    const int tid = threadIdx.x, wid = tid >> 5, lane = tid & 31;
    const int rowBase = blockIdx.x * 128;

#pragma unroll
    for (int i = 0; i < 8; i++) {
        int f = tid + i * 256;
        int r = f >> 4, c16 = f & 15;
        uint32_t off = (uint32_t)r * (LDAB * 2) + c16 * 16;
        int gr = rowBase + r;
        uint4 vh = make_uint4(0, 0, 0, 0), vl = vh;
        if (gr < M) {
            vh = *(const uint4*)(AhiG + (size_t)gr * 128 + c16 * 8);
            vl = *(const uint4*)(AloG + (size_t)gr * 128 + c16 * 8);
        }
        *(uint4*)(smem + SA_HI + off) = vh;
        *(uint4*)(smem + SA_LO + off) = vl;
    }
    __syncthreads();

    const int wm = wid & 1, wn = wid >> 1;
    const int aRow = wm * 64 + (lane & 7) + ((lane >> 3) & 1) * 8;
    const int aCol = ((lane >> 4) & 1) * 8;
    uint32_t aOff[4];
#pragma unroll
    for (int mf = 0; mf < 4; mf++)
        aOff[mf] = sb + (uint32_t)(aRow + mf * 16) * (LDAB * 2) + (uint32_t)aCol * 2;

    float acc[4][4][4];
    gemm_main(acc, aOff, Bfh, Bfl, wn, lane);

    const int quad = lane >> 2, pairc = (lane & 3) * 2;
#pragma unroll
    for (int mf = 0; mf < 4; mf++) {
        int r0 = rowBase + wm * 64 + mf * 16 + quad;
#pragma unroll
        for (int nf = 0; nf < 4; nf++) {
            int c0 = wn * 32 + nf * 8 + pairc;
            if (c0 < 64) {   // left half -> bf16 Y1l, ld 64
                if (r0 < M)
                    *(uint32_t*)(Cl + (size_t)r0 * 64 + c0) = packbf2(acc[mf][nf][0], acc[mf][nf][1]);
                if (r0 + 8 < M)
                    *(uint32_t*)(Cl + (size_t)(r0 + 8) * 64 + c0) = packbf2(acc[mf][nf][2], acc[mf][nf][3]);
            } else {         // right half -> fp32 Y1r, ld 64
                int c1 = c0 - 64;
                if (r0 < M)
                    *(float2*)(Cr + (size_t)r0 * 64 + c1) = make_float2(acc[mf][nf][0], acc[mf][nf][1]);
                if (r0 + 8 < M)
                    *(float2*)(Cr + (size_t)(r0 + 8) * 64 + c1) = make_float2(acc[mf][nf][2], acc[mf][nf][3]);
            }
        }
    }
}

// ---------------- aggregation epilogues (R11 simple-loop form) ------------------
// layer 0: h = relu( inv*sum_j bf16(Zl[j]) + Zr[i] + b0 ), emit bf16 hi/lo
__global__ void k_agg0(const float* __restrict__ b0) {
    int w = (blockIdx.x * blockDim.x + threadIdx.x) >> 5;
    int lane = threadIdx.x & 31;
    if (w >= NN) return;
    int s = g_rowptr[w], e = g_rowptr[w + 1];
    const uint2* Z = (const uint2*)g_Zl;      // 32 uint2 (256B) per row
    float4 acc = make_float4(0.f, 0.f, 0.f, 0.f);
    for (int p = s; p < e; p++) {
        int j = g_col[p];
        uint2 v = Z[(size_t)j * 32 + lane];
        float2 f01 = __bfloat1622float2(*reinterpret_cast<const __nv_bfloat162*>(&v.x));
        float2 f23 = __bfloat1622float2(*reinterpret_cast<const __nv_bfloat162*>(&v.y));
        acc.x += f01.x; acc.y += f01.y; acc.z += f23.x; acc.w += f23.y;
    }
    float inv = g_inv[w];
    float4 r = ((const float4*)g_Zr)[(size_t)w * 32 + lane];
    float4 bb = ((const float4*)b0)[lane];
    float o0 = fmaxf(fmaf(acc.x, inv, r.x + bb.x), 0.f);
    float o1 = fmaxf(fmaf(acc.y, inv, r.y + bb.y), 0.f);
    float o2 = fmaxf(fmaf(acc.z, inv, r.z + bb.z), 0.f);
    float o3 = fmaxf(fmaf(acc.w, inv, r.w + bb.w), 0.f);
    uint32_t h01, l01, h23, l23;
    cvt2(o0, o1, h01, l01);
    cvt2(o2, o3, h23, l23);
    ((uint2*)g_hhi)[(size_t)w * 32 + lane] = make_uint2(h01, h23);
    ((uint2*)g_hlo)[(size_t)w * 32 + lane] = make_uint2(l01, l23);
}

// layer 1: h2 = inv*sum_j bf16(Y1l[j]) + Y1r[i] + b1 (fp32 accum, fp16 out)
__global__ void k_agg1(const float* __restrict__ b1) {
    int w = (blockIdx.x * blockDim.x + threadIdx.x) >> 5;
    int lane = threadIdx.x & 31;
    if (w >= NN) return;
    int s = g_rowptr[w], e = g_rowptr[w + 1];
    const uint32_t* Yl = (const uint32_t*)g_Y1l;   // 32 uint32 (128B) per row
    float2 acc = make_float2(0.f, 0.f);
    for (int p = s; p < e; p++) {
        int j = g_col[p];
        uint32_t v = Yl[(size_t)j * 32 + lane];
        float2 f = __bfloat1622float2(*reinterpret_cast<const __nv_bfloat162*>(&v));
        acc.x += f.x; acc.y += f.y;
    }
    float inv = g_inv[w];
    float2 r = ((const float2*)g_Y1r)[(size_t)w * 32 + lane];
    float2 bb = ((const float2*)b1)[lane];
    float2 o;
    o.x = fmaf(acc.x, inv, r.x + bb.x);
    o.y = fmaf(acc.y, inv, r.y + bb.y);
    __half2 oh = __float22half2_rn(o);
    ((uint32_t*)g_h2)[(size_t)w * 32 + lane] = *reinterpret_cast<uint32_t*>(&oh);
}

// ---------------- edge scoring: 4 edges/warp, 8 lanes/edge ----------------------
__global__ void k_score(const int* __restrict__ pe, const int* __restrict__ ne,
                        float* __restrict__ out) {
    int gw = (blockIdx.x * blockDim.x + threadIdx.x) >> 5;   // warp id
    int lane = threadIdx.x & 31;
    int g = lane >> 3, l8 = lane & 7;
    int e = gw * 4 + g;                 // edge id in [0, 2*NEP); warps never straddle
    if (e >= 2 * NEP) return;
    int a, b;
    if (e < NEP) { a = pe[e]; b = pe[NEP + e]; }
    else         { int q = e - NEP; a = ne[q]; b = ne[NEP + q]; }
    const uint4* H = (const uint4*)g_h2;    // row = 8 uint4 (64 halves)
    uint4 ua = H[(size_t)a * 8 + l8];
    uint4 ub = H[(size_t)b * 8 + l8];
    float s;
    {
        float2 a0 = __half22float2(*reinterpret_cast<const __half2*>(&ua.x));
        float2 b0 = __half22float2(*reinterpret_cast<const __half2*>(&ub.x));
        float2 a1 = __half22float2(*reinterpret_cast<const __half2*>(&ua.y));
        float2 b1 = __half22float2(*reinterpret_cast<const __half2*>(&ub.y));
        float2 a2 = __half22float2(*reinterpret_cast<const __half2*>(&ua.z));
        float2 b2 = __half22float2(*reinterpret_cast<const __half2*>(&ub.z));
        float2 a3 = __half22float2(*reinterpret_cast<const __half2*>(&ua.w));
        float2 b3 = __half22float2(*reinterpret_cast<const __half2*>(&ub.w));
        s = a0.x * b0.x;
        s = fmaf(a0.y, b0.y, s);
        s = fmaf(a1.x, b1.x, s);
        s = fmaf(a1.y, b1.y, s);
        s = fmaf(a2.x, b2.x, s);
        s = fmaf(a2.y, b2.y, s);
        s = fmaf(a3.x, b3.x, s);
        s = fmaf(a3.y, b3.y, s);
    }
    s += __shfl_xor_sync(0xffffffffu, s, 4);
    s += __shfl_xor_sync(0xffffffffu, s, 2);
    s += __shfl_xor_sync(0xffffffffu, s, 1);
    if (l8 == 0) out[e] = s;
}

// ---------------- launcher -----------------------------------------------------
extern "C" void kernel_launch(void* const* d_in, const int* in_sizes, int n_in,
                              void* d_out, int out_size) {
    const float* x   = (const float*)d_in[0];
    const int*   ei  = (const int*)d_in[1];
    const int*   pe  = (const int*)d_in[2];
    const int*   ne  = (const int*)d_in[3];
    const float* Wl0 = (const float*)d_in[4];
    const float* b0  = (const float*)d_in[5];
    const float* Wr0 = (const float*)d_in[6];
    const float* Wl1 = (const float*)d_in[7];
    const float* b1  = (const float*)d_in[8];
    const float* Wr1 = (const float*)d_in[9];
    float* out = (float*)d_out;

    static cudaStream_t s1 = nullptr;
    static cudaEvent_t eF = nullptr, e1 = nullptr;
    if (s1 == nullptr) {
        cudaStreamCreateWithFlags(&s1, cudaStreamNonBlocking);
        cudaEventCreateWithFlags(&eF, cudaEventDisableTiming);
        cudaEventCreateWithFlags(&e1, cudaEventDisableTiming);
        cudaFuncSetAttribute(k_mma0dual, cudaFuncAttributeMaxDynamicSharedMemorySize, SMEM_MMA);
        cudaFuncSetAttribute(k_mma1,     cudaFuncAttributeMaxDynamicSharedMemorySize, SMEM_MMA);
    }

    __nv_bfloat16 *pZl, *pHhi, *pHlo, *pY1l;
    float *pZr, *pY1r;
    uint2 *pBfh, *pBfl;
    int *pDeg;
    cudaGetSymbolAddress((void**)&pZl,  g_Zl);
    cudaGetSymbolAddress((void**)&pZr,  g_Zr);
    cudaGetSymbolAddress((void**)&pY1l, g_Y1l);
    cudaGetSymbolAddress((void**)&pY1r, g_Y1r);
    cudaGetSymbolAddress((void**)&pHhi, g_hhi);
    cudaGetSymbolAddress((void**)&pHlo, g_hlo);
    cudaGetSymbolAddress((void**)&pBfh, g_Bfh);
    cudaGetSymbolAddress((void**)&pBfl, g_Bfl);
    cudaGetSymbolAddress((void**)&pDeg, g_deg);

    const int NB = (NN + 1023) / 1024;   // 98
    const int GX = (NN + 127) / 128;     // 782

    // fork: s1 branches off the main (captured) stream
    cudaEventRecord(eF, 0);
    cudaStreamWaitEvent(s1, eF, 0);

    // branch A (s1): weights -> merged layer-0 GEMM (A staged once, 2 passes)
    k_cvt_w<<<48, 256, 0, s1>>>(Wl0, Wr0, Wl1, Wr1);
    k_mma0dual<<<GX, 256, SMEM_MMA, s1>>>(x, pBfh, pBfl, pBfh + 4096, pBfl + 4096,
                                          pZl, pZr, NN);

    // branch B (main stream): CSR build
    cudaMemsetAsync(pDeg, 0, NN * sizeof(int), 0);
    k_count<<<(NE + 255) / 256, 256>>>(ei);
    k_scan1<<<NB, 256>>>();
    k_scan2<<<1, 128>>>(NB);
    k_scan3<<<NB, 256>>>();
    k_scatter<<<(NE + 255) / 256, 256>>>(ei);

    // join
    cudaEventRecord(e1, s1);
    cudaStreamWaitEvent(0, e1, 0);

    // layer 0 aggregate, layer 1 (split bf16/fp32 out), layer-1 aggregate, scores
    k_agg0<<<(NN * 32 + 255) / 256, 256>>>(b0);
    k_mma1<<<GX, 256, SMEM_MMA>>>(pHhi, pHlo, pBfh + 8192, pBfl + 8192, pY1l, pY1r, NN);
    k_agg1<<<(NN * 32 + 255) / 256, 256>>>(b1);
    // 4 edges per warp: 2*NEP/4 = 250K warps -> 31250 blocks of 256 threads
    k_score<<<(2 * NEP / 4 * 32) / 256, 256>>>(pe, ne, out);
}

// round 14
// speedup vs baseline: 1.1768x; 1.0877x over previous
#include <cuda_runtime.h>
#include <cuda_bf16.h>
#include <cuda_fp16.h>
#include <cstdint>

#define NN 100000
#define NE 1600000
#define NEP 500000

// ---------------- scratch (device globals) ------------------------------------
__device__ int   g_deg[NN];
__device__ int   g_rowptr[NN + 1];
__device__ int   g_fill[NN];
__device__ float g_inv[NN];
__device__ int   g_col[NE];
__device__ int   g_bsum[128];
__device__ __nv_bfloat16 g_Zl[(size_t)NN * 128]; // x @ W_l0  (bf16 — gathered 16x)
__device__ float g_Zr[(size_t)NN * 128];          // x @ W_r0  (fp32 — read once)
__device__ __half g_h16[(size_t)NN * 128];        // layer-0 output (fp16)
__device__ __nv_bfloat16 g_Y1l[(size_t)NN * 64];  // h @ W_l1 (bf16 — gathered 16x)
__device__ float g_Y1r[(size_t)NN * 64];          // h @ W_r1 (fp32 — read once)
__device__ __half g_h2[(size_t)NN * 64];          // layer-1 output (fp16, 128B rows)
// B fragments: compensated bf16 hi/lo for layer 0; fp16 for layer 1.
__device__ uint2 g_Bfh[2 * 4096];
__device__ uint2 g_Bfl[2 * 4096];
__device__ uint2 g_Bq1[4096];

// ---------------- helpers -------------------------------------------------------
static __device__ __forceinline__ uint32_t smem_u32(const void* p) {
    uint32_t a;
    asm("{ .reg .u64 t; cvta.to.shared.u64 t, %1; cvt.u32.u64 %0, t; }" : "=r"(a) : "l"(p));
    return a;
}

static __device__ __forceinline__ void ldm_x4(uint32_t r[4], uint32_t addr) {
    asm volatile("ldmatrix.sync.aligned.m8n8.x4.shared.b16 {%0,%1,%2,%3}, [%4];"
        : "=r"(r[0]), "=r"(r[1]), "=r"(r[2]), "=r"(r[3]) : "r"(addr));
}

static __device__ __forceinline__ void mma16816(float c[4], const uint32_t a[4],
                                                const uint32_t b0, const uint32_t b1) {
    asm volatile("mma.sync.aligned.m16n8k16.row.col.f32.bf16.bf16.f32 "
        "{%0,%1,%2,%3}, {%4,%5,%6,%7}, {%8,%9}, {%0,%1,%2,%3};"
        : "+f"(c[0]), "+f"(c[1]), "+f"(c[2]), "+f"(c[3])
        : "r"(a[0]), "r"(a[1]), "r"(a[2]), "r"(a[3]), "r"(b0), "r"(b1));
}

static __device__ __forceinline__ void mma16816h(float c[4], const uint32_t a[4],
                                                 const uint32_t b0, const uint32_t b1) {
    asm volatile("mma.sync.aligned.m16n8k16.row.col.f32.f16.f16.f32 "
        "{%0,%1,%2,%3}, {%4,%5,%6,%7}, {%8,%9}, {%0,%1,%2,%3};"
        : "+f"(c[0]), "+f"(c[1]), "+f"(c[2]), "+f"(c[3])
        : "r"(a[0]), "r"(a[1]), "r"(a[2]), "r"(a[3]), "r"(b0), "r"(b1));
}

// pack two fp32 into bf16-hi pair and bf16-lo (residual) pair
static __device__ __forceinline__ void cvt2(float a, float b, uint32_t& hi, uint32_t& lo) {
    __nv_bfloat16 ha = __float2bfloat16(a), hb = __float2bfloat16(b);
    hi = (uint32_t)__bfloat16_as_ushort(ha) | ((uint32_t)__bfloat16_as_ushort(hb) << 16);
    __nv_bfloat16 la = __float2bfloat16(a - __bfloat162float(ha));
    __nv_bfloat16 lb = __float2bfloat16(b - __bfloat162float(hb));
    lo = (uint32_t)__bfloat16_as_ushort(la) | ((uint32_t)__bfloat16_as_ushort(lb) << 16);
}

static __device__ __forceinline__ uint32_t packbf2(float a, float b) {
    __nv_bfloat162 p = __float22bfloat162_rn(make_float2(a, b));
    return *reinterpret_cast<uint32_t*>(&p);
}

static __device__ __forceinline__ uint32_t packh2(float a, float b) {
    __half2 p = __floats2half2_rn(a, b);
    return *reinterpret_cast<uint32_t*>(&p);
}

// ---------------- CSR build ---------------------------------------------------
__global__ void k_count(const int* __restrict__ ei) {
    int e = blockIdx.x * blockDim.x + threadIdx.x;
    if (e < NE) atomicAdd(&g_deg[ei[NE + e]], 1);
}

__global__ void k_scan1() {
    int t = threadIdx.x, b = blockIdx.x;
    int i4 = b * 256 + t;
    int s = 0;
    if (i4 < NN / 4) {
        int4 d = ((const int4*)g_deg)[i4];
        s = d.x + d.y + d.z + d.w;
    }
    for (int o = 16; o; o >>= 1) s += __shfl_xor_sync(0xffffffffu, s, o);
    __shared__ int ws[8];
    if ((t & 31) == 0) ws[t >> 5] = s;
    __syncthreads();
    if (t == 0) {
        int tot = 0;
#pragma unroll
        for (int w = 0; w < 8; w++) tot += ws[w];
        g_bsum[b] = tot;
    }
}

__global__ void k_scan2(int nb) {
    __shared__ int s[128];
    int t = threadIdx.x;
    int v = (t < nb) ? g_bsum[t] : 0;
    s[t] = v;
    __syncthreads();
#pragma unroll
    for (int o = 1; o < 128; o <<= 1) {
        int u = (t >= o) ? s[t - o] : 0;
        __syncthreads();
        s[t] += u;
        __syncthreads();
    }
    if (t < nb) g_bsum[t] = s[t] - v;   // exclusive
    if (t == 0) g_rowptr[NN] = NE;
}

__global__ void k_scan3() {
    int t = threadIdx.x, b = blockIdx.x;
    int lane = t & 31, wid = t >> 5;
    int i4 = b * 256 + t;
    int4 d = make_int4(0, 0, 0, 0);
    bool act = (i4 < NN / 4);
    if (act) d = ((const int4*)g_deg)[i4];
    int e0 = 0, e1 = d.x, e2 = d.x + d.y, e3 = d.x + d.y + d.z;
    int tsum = e3 + d.w;
    int v = tsum;
#pragma unroll
    for (int o = 1; o < 32; o <<= 1) {
        int u = __shfl_up_sync(0xffffffffu, v, o);
        if (lane >= o) v += u;
    }
    __shared__ int wsum[8], woff[8];
    if (lane == 31) wsum[wid] = v;
    __syncthreads();
    if (t == 0) {
        int r = 0;
#pragma unroll
        for (int w = 0; w < 8; w++) { int tmp = wsum[w]; woff[w] = r; r += tmp; }
    }
    __syncthreads();
    if (act) {
        int base = g_bsum[b] + woff[wid] + (v - tsum);
        int i = i4 * 4;
        g_rowptr[i + 0] = base + e0;  g_fill[i + 0] = base + e0;
        g_rowptr[i + 1] = base + e1;  g_fill[i + 1] = base + e1;
        g_rowptr[i + 2] = base + e2;  g_fill[i + 2] = base + e2;
        g_rowptr[i + 3] = base + e3;  g_fill[i + 3] = base + e3;
        g_inv[i + 0] = 1.0f / (float)max(d.x, 1);
        g_inv[i + 1] = 1.0f / (float)max(d.y, 1);
        g_inv[i + 2] = 1.0f / (float)max(d.z, 1);
        g_inv[i + 3] = 1.0f / (float)max(d.w, 1);
    }
}

__global__ void k_scatter(const int* __restrict__ ei) {
    int e = blockIdx.x * blockDim.x + threadIdx.x;
    if (e < NE) {
        int dst = ei[NE + e];
        int p = atomicAdd(&g_fill[dst], 1);
        g_col[p] = ei[e];
    }
}

// ---------------- weight conversion ---------------------------------------------
// m=0: Wl0^T (bf16 hi/lo), m=1: Wr0^T (bf16 hi/lo), m=2: [Wl1|Wr1]^T (fp16)
__global__ void k_cvt_w(const float* __restrict__ Wl0, const float* __restrict__ Wr0,
                        const float* __restrict__ Wl1, const float* __restrict__ Wr1) {
    int idx = blockIdx.x * blockDim.x + threadIdx.x;
    if (idx >= 3 * 4096) return;
    int lane = idx & 31;
    int n8   = (idx >> 5) & 15;
    int ks   = (idx >> 9) & 7;
    int m    = idx >> 12;
    int n  = n8 * 8 + (lane >> 2);
    int k0 = ks * 16 + (lane & 3) * 2;
    auto w = [&](int k) -> float {
        if (m == 0) return Wl0[k * 128 + n];
        if (m == 1) return Wr0[k * 128 + n];
        return (n < 64) ? Wl1[k * 64 + n] : Wr1[k * 64 + (n - 64)];
    };
    float v0 = w(k0), v1 = w(k0 + 1), v2 = w(k0 + 8), v3 = w(k0 + 9);
    if (m < 2) {
        uint32_t h0, l0, h1, l1;
        cvt2(v0, v1, h0, l0);
        cvt2(v2, v3, h1, l1);
        g_Bfh[idx] = make_uint2(h0, h1);
        g_Bfl[idx] = make_uint2(l0, l1);
    } else {
        g_Bq1[idx - 8192] = make_uint2(packh2(v0, v1), packh2(v2, v3));
    }
}

// ---------------- HMMA GEMM core (compensated bf16, layer 0) --------------------
#define LDAB 136
#define TILE_B (128 * LDAB * 2)          // 34816 bytes per tile
#define SA_HI 0
#define SA_LO TILE_B
#define SMEM_MMA (2 * TILE_B)            // 69632 bytes

static __device__ __forceinline__ void gemm_main(float (&acc)[4][4][4],
                                                 const uint32_t aOff[4],
                                                 const uint2* __restrict__ Bfh,
                                                 const uint2* __restrict__ Bfl,
                                                 int wn, int lane) {
#pragma unroll
    for (int mf = 0; mf < 4; mf++)
#pragma unroll
        for (int nf = 0; nf < 4; nf++)
#pragma unroll
            for (int q = 0; q < 4; q++) acc[mf][nf][q] = 0.f;
#pragma unroll
    for (int ks = 0; ks < 8; ks++) {
        const uint32_t kb = ks * 32;       // 16 elems = 32 bytes
        const int fibase = (ks * 16 + wn * 4) * 32 + lane;
        uint2 bh[4], bl[4];
#pragma unroll
        for (int nf = 0; nf < 4; nf++) {
            bh[nf] = Bfh[fibase + nf * 32];
            bl[nf] = Bfl[fibase + nf * 32];
        }
        uint32_t a[4][4];
#pragma unroll
        for (int mf = 0; mf < 4; mf++) ldm_x4(a[mf], aOff[mf] + SA_HI + kb);
#pragma unroll
        for (int mf = 0; mf < 4; mf++)
#pragma unroll
            for (int nf = 0; nf < 4; nf++)
                mma16816(acc[mf][nf], a[mf], bh[nf].x, bh[nf].y);
#pragma unroll
        for (int mf = 0; mf < 4; mf++)
#pragma unroll
            for (int nf = 0; nf < 4; nf++)
                mma16816(acc[mf][nf], a[mf], bl[nf].x, bl[nf].y);
#pragma unroll
        for (int mf = 0; mf < 4; mf++) ldm_x4(a[mf], aOff[mf] + SA_LO + kb);
#pragma unroll
        for (int mf = 0; mf < 4; mf++)
#pragma unroll
            for (int nf = 0; nf < 4; nf++)
                mma16816(acc[mf][nf], a[mf], bh[nf].x, bh[nf].y);
    }
}

// merged layer-0 GEMM: stage/convert A ONCE, two MMA passes.
__global__ __launch_bounds__(256, 2)
void k_mma0dual(const float* __restrict__ A,
                const uint2* __restrict__ Bfh0, const uint2* __restrict__ Bfl0,
                const uint2* __restrict__ Bfh1, const uint2* __restrict__ Bfl1,
                __nv_bfloat16* __restrict__ Cl, float* __restrict__ Cr, int M) {
    extern __shared__ char smem[];
    const uint32_t sb = smem_u32(smem);
    const int tid = threadIdx.x, wid = tid >> 5, lane = tid & 31;
    const int rowBase = blockIdx.x * 128;

#pragma unroll
    for (int i = 0; i < 8; i++) {
        int f = tid + i * 256;
        int r = f >> 4, c16 = f & 15;
        uint32_t off = (uint32_t)r * (LDAB * 2) + c16 * 16;
        int gr = rowBase + r;
        float4 v0 = make_float4(0.f, 0.f, 0.f, 0.f), v1 = v0;
        if (gr < M) {
            const float* ap = A + (size_t)gr * 128 + c16 * 8;
            v0 = *(const float4*)ap;
            v1 = *(const float4*)(ap + 4);
        }
        uint4 hi, lo;
        cvt2(v0.x, v0.y, hi.x, lo.x);
        cvt2(v0.z, v0.w, hi.y, lo.y);
        cvt2(v1.x, v1.y, hi.z, lo.z);
        cvt2(v1.z, v1.w, hi.w, lo.w);
        *(uint4*)(smem + SA_HI + off) = hi;
        *(uint4*)(smem + SA_LO + off) = lo;
    }
    __syncthreads();

    const int wm = wid & 1, wn = wid >> 1;
    const int aRow = wm * 64 + (lane & 7) + ((lane >> 3) & 1) * 8;
    const int aCol = ((lane >> 4) & 1) * 8;
    uint32_t aOff[4];
#pragma unroll
    for (int mf = 0; mf < 4; mf++)
        aOff[mf] = sb + (uint32_t)(aRow + mf * 16) * (LDAB * 2) + (uint32_t)aCol * 2;

    const int quad = lane >> 2, pairc = (lane & 3) * 2;
    float acc[4][4][4];

    // pass 1: Zl (bf16 out)
    gemm_main(acc, aOff, Bfh0, Bfl0, wn, lane);
#pragma unroll
    for (int mf = 0; mf < 4; mf++) {
        int r0 = rowBase + wm * 64 + mf * 16 + quad;
#pragma unroll
        for (int nf = 0; nf < 4; nf++) {
            int c0 = wn * 32 + nf * 8 + pairc;
            if (r0 < M)
                *(uint32_t*)(Cl + (size_t)r0 * 128 + c0) = packbf2(acc[mf][nf][0], acc[mf][nf][1]);
            if (r0 + 8 < M)
                *(uint32_t*)(Cl + (size_t)(r0 + 8) * 128 + c0) = packbf2(acc[mf][nf][2], acc[mf][nf][3]);
        }
    }

    // pass 2: Zr (fp32 out)
    gemm_main(acc, aOff, Bfh1, Bfl1, wn, lane);
#pragma unroll
    for (int mf = 0; mf < 4; mf++) {
        int r0 = rowBase + wm * 64 + mf * 16 + quad;
#pragma unroll
        for (int nf = 0; nf < 4; nf++) {
            int c0 = wn * 32 + nf * 8 + pairc;
            if (r0 < M)
                *(float2*)(Cr + (size_t)r0 * 128 + c0) = make_float2(acc[mf][nf][0], acc[mf][nf][1]);
            if (r0 + 8 < M)
                *(float2*)(Cr + (size_t)(r0 + 8) * 128 + c0) = make_float2(acc[mf][nf][2], acc[mf][nf][3]);
        }
    }
}

// layer-1 GEMM: single-pass fp16 (A = h fp16, B = [Wl1|Wr1] fp16).
// One smem tile (34.8KB). Split out: Y1l bf16 (ld 64) + Y1r fp32 (ld 64).
__global__ __launch_bounds__(256, 2)
void k_mma1(const __half* __restrict__ A, const uint2* __restrict__ Bq,
            __nv_bfloat16* __restrict__ Cl, float* __restrict__ Cr, int M) {
    extern __shared__ char smem[];
    const uint32_t sb = smem_u32(smem);
    const int tid = threadIdx.x, wid = tid >> 5, lane = tid & 31;
    const int rowBase = blockIdx.x * 128;

#pragma unroll
    for (int i = 0; i < 8; i++) {
        int f = tid + i * 256;
        int r = f >> 4, c16 = f & 15;
        uint32_t off = (uint32_t)r * (LDAB * 2) + c16 * 16;
        int gr = rowBase + r;
        uint4 v = make_uint4(0, 0, 0, 0);
        if (gr < M) v = *(const uint4*)(A + (size_t)gr * 128 + c16 * 8);
        *(uint4*)(smem + off) = v;
    }
    __syncthreads();

    const int wm = wid & 1, wn = wid >> 1;
    const int aRow = wm * 64 + (lane & 7) + ((lane >> 3) & 1) * 8;
    const int aCol = ((lane >> 4) & 1) * 8;
    uint32_t aOff[4];
#pragma unroll
    for (int mf = 0; mf < 4; mf++)
        aOff[mf] = sb + (uint32_t)(aRow + mf * 16) * (LDAB * 2) + (uint32_t)aCol * 2;

    float acc[4][4][4];
#pragma unroll
    for (int mf = 0; mf < 4; mf++)
#pragma unroll
        for (int nf = 0; nf < 4; nf++)
#pragma unroll
            for (int q = 0; q < 4; q++) acc[mf][nf][q] = 0.f;

#pragma unroll
    for (int ks = 0; ks < 8; ks++) {
        const uint32_t kb = ks * 32;
        const int fibase = (ks * 16 + wn * 4) * 32 + lane;
        uint2 bq[4];
#pragma unroll
        for (int nf = 0; nf < 4; nf++) bq[nf] = Bq[fibase + nf * 32];
        uint32_t a[4][4];
#pragma unroll
        for (int mf = 0; mf < 4; mf++) ldm_x4(a[mf], aOff[mf] + kb);
#pragma unroll
        for (int mf = 0; mf < 4; mf++)
#pragma unroll
            for (int nf = 0; nf < 4; nf++)
                mma16816h(acc[mf][nf], a[mf], bq[nf].x, bq[nf].y);
    }

    const int quad = lane >> 2, pairc = (lane & 3) * 2;
#pragma unroll
    for (int mf = 0; mf < 4; mf++) {
        int r0 = rowBase + wm * 64 + mf * 16 + quad;
#pragma unroll
        for (int nf = 0; nf < 4; nf++) {
            int c0 = wn * 32 + nf * 8 + pairc;
            if (c0 < 64) {
                if (r0 < M)
                    *(uint32_t*)(Cl + (size_t)r0 * 64 + c0) = packbf2(acc[mf][nf][0], acc[mf][nf][1]);
                if (r0 + 8 < M)
                    *(uint32_t*)(Cl + (size_t)(r0 + 8) * 64 + c0) = packbf2(acc[mf][nf][2], acc[mf][nf][3]);
            } else {
                int c1 = c0 - 64;
                if (r0 < M)
                    *(float2*)(Cr + (size_t)r0 * 64 + c1) = make_float2(acc[mf][nf][0], acc[mf][nf][1]);
                if (r0 + 8 < M)
                    *(float2*)(Cr + (size_t)(r0 + 8) * 64 + c1) = make_float2(acc[mf][nf][2], acc[mf][nf][3]);
            }
        }
    }
}

// ---------------- aggregation epilogues ------------------------------------------
// layer 0: h = relu( inv*sum_j bf16(Zl[j]) + Zr[i] + b0 ), emit fp16
__global__ void k_agg0(const float* __restrict__ b0) {
    int w = (blockIdx.x * blockDim.x + threadIdx.x) >> 5;
    int lane = threadIdx.x & 31;
    if (w >= NN) return;
    int s = g_rowptr[w], e = g_rowptr[w + 1];
    const uint2* Z = (const uint2*)g_Zl;      // 32 uint2 (256B) per row
    float4 acc = make_float4(0.f, 0.f, 0.f, 0.f);
    for (int p = s; p < e; p++) {
        int j = g_col[p];
        uint2 v = Z[(size_t)j * 32 + lane];
        float2 f01 = __bfloat1622float2(*reinterpret_cast<const __nv_bfloat162*>(&v.x));
        float2 f23 = __bfloat1622float2(*reinterpret_cast<const __nv_bfloat162*>(&v.y));
        acc.x += f01.x; acc.y += f01.y; acc.z += f23.x; acc.w += f23.y;
    }
    float inv = g_inv[w];
    float4 r = ((const float4*)g_Zr)[(size_t)w * 32 + lane];
    float4 bb = ((const float4*)b0)[lane];
    float o0 = fmaxf(fmaf(acc.x, inv, r.x + bb.x), 0.f);
    float o1 = fmaxf(fmaf(acc.y, inv, r.y + bb.y), 0.f);
    float o2 = fmaxf(fmaf(acc.z, inv, r.z + bb.z), 0.f);
    float o3 = fmaxf(fmaf(acc.w, inv, r.w + bb.w), 0.f);
    ((uint2*)g_h16)[(size_t)w * 32 + lane] = make_uint2(packh2(o0, o1), packh2(o2, o3));
}

// layer 1: h2 = inv*sum_j bf16(Y1l[j]) + Y1r[i] + b1 (fp32 accum, fp16 out)
__global__ void k_agg1(const float* __restrict__ b1) {
    int w = (blockIdx.x * blockDim.x + threadIdx.x) >> 5;
    int lane = threadIdx.x & 31;
    if (w >= NN) return;
    int s = g_rowptr[w], e = g_rowptr[w + 1];
    const uint32_t* Yl = (const uint32_t*)g_Y1l;   // 32 uint32 (128B) per row
    float2 acc = make_float2(0.f, 0.f);
    for (int p = s; p < e; p++) {
        int j = g_col[p];
        uint32_t v = Yl[(size_t)j * 32 + lane];
        float2 f = __bfloat1622float2(*reinterpret_cast<const __nv_bfloat162*>(&v));
        acc.x += f.x; acc.y += f.y;
    }
    float inv = g_inv[w];
    float2 r = ((const float2*)g_Y1r)[(size_t)w * 32 + lane];
    float2 bb = ((const float2*)b1)[lane];
    float ox = fmaf(acc.x, inv, r.x + bb.x);
    float oy = fmaf(acc.y, inv, r.y + bb.y);
    ((uint32_t*)g_h2)[(size_t)w * 32 + lane] = packh2(ox, oy);
}

// ---------------- edge scoring: 4 edges/warp, 8 lanes/edge ----------------------
__global__ void k_score(const int* __restrict__ pe, const int* __restrict__ ne,
                        float* __restrict__ out) {
    int gw = (blockIdx.x * blockDim.x + threadIdx.x) >> 5;   // warp id
    int lane = threadIdx.x & 31;
    int g = lane >> 3, l8 = lane & 7;
    int e = gw * 4 + g;                 // edge id in [0, 2*NEP); warps never straddle
    if (e >= 2 * NEP) return;
    int a, b;
    if (e < NEP) { a = pe[e]; b = pe[NEP + e]; }
    else         { int q = e - NEP; a = ne[q]; b = ne[NEP + q]; }
    const uint4* H = (const uint4*)g_h2;    // row = 8 uint4 (64 halves)
    uint4 ua = H[(size_t)a * 8 + l8];
    uint4 ub = H[(size_t)b * 8 + l8];
    float s;
    {
        float2 a0 = __half22float2(*reinterpret_cast<const __half2*>(&ua.x));
        float2 b0 = __half22float2(*reinterpret_cast<const __half2*>(&ub.x));
        float2 a1 = __half22float2(*reinterpret_cast<const __half2*>(&ua.y));
        float2 b1 = __half22float2(*reinterpret_cast<const __half2*>(&ub.y));
        float2 a2 = __half22float2(*reinterpret_cast<const __half2*>(&ua.z));
        float2 b2 = __half22float2(*reinterpret_cast<const __half2*>(&ub.z));
        float2 a3 = __half22float2(*reinterpret_cast<const __half2*>(&ua.w));
        float2 b3 = __half22float2(*reinterpret_cast<const __half2*>(&ub.w));
        s = a0.x * b0.x;
        s = fmaf(a0.y, b0.y, s);
        s = fmaf(a1.x, b1.x, s);
        s = fmaf(a1.y, b1.y, s);
        s = fmaf(a2.x, b2.x, s);
        s = fmaf(a2.y, b2.y, s);
        s = fmaf(a3.x, b3.x, s);
        s = fmaf(a3.y, b3.y, s);
    }
    s += __shfl_xor_sync(0xffffffffu, s, 4);
    s += __shfl_xor_sync(0xffffffffu, s, 2);
    s += __shfl_xor_sync(0xffffffffu, s, 1);
    if (l8 == 0) out[e] = s;
}

// ---------------- launcher -----------------------------------------------------
extern "C" void kernel_launch(void* const* d_in, const int* in_sizes, int n_in,
                              void* d_out, int out_size) {
    const float* x   = (const float*)d_in[0];
    const int*   ei  = (const int*)d_in[1];
    const int*   pe  = (const int*)d_in[2];
    const int*   ne  = (const int*)d_in[3];
    const float* Wl0 = (const float*)d_in[4];
    const float* b0  = (const float*)d_in[5];
    const float* Wr0 = (const float*)d_in[6];
    const float* Wl1 = (const float*)d_in[7];
    const float* b1  = (const float*)d_in[8];
    const float* Wr1 = (const float*)d_in[9];
    float* out = (float*)d_out;

    static cudaStream_t s1 = nullptr;
    static cudaEvent_t eF = nullptr, e1 = nullptr;
    if (s1 == nullptr) {
        cudaStreamCreateWithFlags(&s1, cudaStreamNonBlocking);
        cudaEventCreateWithFlags(&eF, cudaEventDisableTiming);
        cudaEventCreateWithFlags(&e1, cudaEventDisableTiming);
        cudaFuncSetAttribute(k_mma0dual, cudaFuncAttributeMaxDynamicSharedMemorySize, SMEM_MMA);
        cudaFuncSetAttribute(k_mma1,     cudaFuncAttributeMaxDynamicSharedMemorySize, TILE_B);
    }

    __nv_bfloat16 *pZl, *pY1l;
    __half *pH16;
    float *pZr, *pY1r;
    uint2 *pBfh, *pBfl, *pBq1;
    int *pDeg;
    cudaGetSymbolAddress((void**)&pZl,  g_Zl);
    cudaGetSymbolAddress((void**)&pZr,  g_Zr);
    cudaGetSymbolAddress((void**)&pH16, g_h16);
    cudaGetSymbolAddress((void**)&pY1l, g_Y1l);
    cudaGetSymbolAddress((void**)&pY1r, g_Y1r);
    cudaGetSymbolAddress((void**)&pBfh, g_Bfh);
    cudaGetSymbolAddress((void**)&pBfl, g_Bfl);
    cudaGetSymbolAddress((void**)&pBq1, g_Bq1);
    cudaGetSymbolAddress((void**)&pDeg, g_deg);

    const int NB = (NN + 1023) / 1024;   // 98
    const int GX = (NN + 127) / 128;     // 782

    // fork: s1 branches off the main (captured) stream
    cudaEventRecord(eF, 0);
    cudaStreamWaitEvent(s1, eF, 0);

    // branch A (s1): weights -> merged layer-0 GEMM (A staged once, 2 passes)
    k_cvt_w<<<48, 256, 0, s1>>>(Wl0, Wr0, Wl1, Wr1);
    k_mma0dual<<<GX, 256, SMEM_MMA, s1>>>(x, pBfh, pBfl, pBfh + 4096, pBfl + 4096,
                                          pZl, pZr, NN);

    // branch B (main stream): CSR build
    cudaMemsetAsync(pDeg, 0, NN * sizeof(int), 0);
    k_count<<<(NE + 255) / 256, 256>>>(ei);
    k_scan1<<<NB, 256>>>();
    k_scan2<<<1, 128>>>(NB);
    k_scan3<<<NB, 256>>>();
    k_scatter<<<(NE + 255) / 256, 256>>>(ei);

    // join
    cudaEventRecord(e1, s1);
    cudaStreamWaitEvent(0, e1, 0);

    // layer 0 aggregate (fp16 h), layer 1 fp16 GEMM, layer-1 aggregate, scores
    k_agg0<<<(NN * 32 + 255) / 256, 256>>>(b0);
    k_mma1<<<GX, 256, TILE_B>>>(pH16, pBq1, pY1l, pY1r, NN);
    k_agg1<<<(NN * 32 + 255) / 256, 256>>>(b1);
    // 4 edges per warp: 2*NEP/4 = 250K warps -> 31250 blocks of 256 threads
    k_score<<<(2 * NEP / 4 * 32) / 256, 256>>>(pe, ne, out);
}

// round 15
// speedup vs baseline: 1.2710x; 1.0801x over previous
#include <cuda_runtime.h>
#include <cuda_bf16.h>
#include <cuda_fp16.h>
#include <cstdint>

#define NN 100000
#define NE 1600000
#define NEP 500000

// ---------------- scratch (device globals) ------------------------------------
__device__ int   g_deg[NN];
__device__ int   g_rowptr[NN + 1];
__device__ int   g_fill[NN];
__device__ float g_inv[NN];
__device__ int   g_col[NE];
__device__ int   g_bsum[128];
__device__ __half g_Zl[(size_t)NN * 128];         // x @ W_l0  (fp16 — gathered 16x)
__device__ float g_Zr[(size_t)NN * 128];          // x @ W_r0  (fp32 — read once)
__device__ __half g_h16[(size_t)NN * 128];        // layer-0 output (fp16)
__device__ __nv_bfloat16 g_Y1l[(size_t)NN * 64];  // h @ W_l1 (bf16 — gathered 16x)
__device__ float g_Y1r[(size_t)NN * 64];          // h @ W_r1 (fp32 — read once)
__device__ __half g_h2[(size_t)NN * 64];          // layer-1 output (fp16, 128B rows)
// B fragments (fp16), per-lane mma layout: m=0 Wl0^T, m=1 Wr0^T, m=2 [Wl1|Wr1]^T
__device__ uint2 g_Bq[3 * 4096];

// ---------------- helpers -------------------------------------------------------
static __device__ __forceinline__ uint32_t smem_u32(const void* p) {
    uint32_t a;
    asm("{ .reg .u64 t; cvta.to.shared.u64 t, %1; cvt.u32.u64 %0, t; }" : "=r"(a) : "l"(p));
    return a;
}

static __device__ __forceinline__ void ldm_x4(uint32_t r[4], uint32_t addr) {
    asm volatile("ldmatrix.sync.aligned.m8n8.x4.shared.b16 {%0,%1,%2,%3}, [%4];"
        : "=r"(r[0]), "=r"(r[1]), "=r"(r[2]), "=r"(r[3]) : "r"(addr));
}

static __device__ __forceinline__ void mma16816h(float c[4], const uint32_t a[4],
                                                 const uint32_t b0, const uint32_t b1) {
    asm volatile("mma.sync.aligned.m16n8k16.row.col.f32.f16.f16.f32 "
        "{%0,%1,%2,%3}, {%4,%5,%6,%7}, {%8,%9}, {%0,%1,%2,%3};"
        : "+f"(c[0]), "+f"(c[1]), "+f"(c[2]), "+f"(c[3])
        : "r"(a[0]), "r"(a[1]), "r"(a[2]), "r"(a[3]), "r"(b0), "r"(b1));
}

static __device__ __forceinline__ uint32_t packbf2(float a, float b) {
    __nv_bfloat162 p = __float22bfloat162_rn(make_float2(a, b));
    return *reinterpret_cast<uint32_t*>(&p);
}

static __device__ __forceinline__ uint32_t packh2(float a, float b) {
    __half2 p = __floats2half2_rn(a, b);
    return *reinterpret_cast<uint32_t*>(&p);
}

// ---------------- CSR build ---------------------------------------------------
__global__ void k_count(const int* __restrict__ ei) {
    int e = blockIdx.x * blockDim.x + threadIdx.x;
    if (e < NE) atomicAdd(&g_deg[ei[NE + e]], 1);
}

__global__ void k_scan1() {
    int t = threadIdx.x, b = blockIdx.x;
    int i4 = b * 256 + t;
    int s = 0;
    if (i4 < NN / 4) {
        int4 d = ((const int4*)g_deg)[i4];
        s = d.x + d.y + d.z + d.w;
    }
    for (int o = 16; o; o >>= 1) s += __shfl_xor_sync(0xffffffffu, s, o);
    __shared__ int ws[8];
    if ((t & 31) == 0) ws[t >> 5] = s;
    __syncthreads();
    if (t == 0) {
        int tot = 0;
#pragma unroll
        for (int w = 0; w < 8; w++) tot += ws[w];
        g_bsum[b] = tot;
    }
}

__global__ void k_scan2(int nb) {
    __shared__ int s[128];
    int t = threadIdx.x;
    int v = (t < nb) ? g_bsum[t] : 0;
    s[t] = v;
    __syncthreads();
#pragma unroll
    for (int o = 1; o < 128; o <<= 1) {
        int u = (t >= o) ? s[t - o] : 0;
        __syncthreads();
        s[t] += u;
        __syncthreads();
    }
    if (t < nb) g_bsum[t] = s[t] - v;   // exclusive
    if (t == 0) g_rowptr[NN] = NE;
}

__global__ void k_scan3() {
    int t = threadIdx.x, b = blockIdx.x;
    int lane = t & 31, wid = t >> 5;
    int i4 = b * 256 + t;
    int4 d = make_int4(0, 0, 0, 0);
    bool act = (i4 < NN / 4);
    if (act) d = ((const int4*)g_deg)[i4];
    int e0 = 0, e1 = d.x, e2 = d.x + d.y, e3 = d.x + d.y + d.z;
    int tsum = e3 + d.w;
    int v = tsum;
#pragma unroll
    for (int o = 1; o < 32; o <<= 1) {
        int u = __shfl_up_sync(0xffffffffu, v, o);
        if (lane >= o) v += u;
    }
    __shared__ int wsum[8], woff[8];
    if (lane == 31) wsum[wid] = v;
    __syncthreads();
    if (t == 0) {
        int r = 0;
#pragma unroll
        for (int w = 0; w < 8; w++) { int tmp = wsum[w]; woff[w] = r; r += tmp; }
    }
    __syncthreads();
    if (act) {
        int base = g_bsum[b] + woff[wid] + (v - tsum);
        int i = i4 * 4;
        g_rowptr[i + 0] = base + e0;  g_fill[i + 0] = base + e0;
        g_rowptr[i + 1] = base + e1;  g_fill[i + 1] = base + e1;
        g_rowptr[i + 2] = base + e2;  g_fill[i + 2] = base + e2;
        g_rowptr[i + 3] = base + e3;  g_fill[i + 3] = base + e3;
        g_inv[i + 0] = 1.0f / (float)max(d.x, 1);
        g_inv[i + 1] = 1.0f / (float)max(d.y, 1);
        g_inv[i + 2] = 1.0f / (float)max(d.z, 1);
        g_inv[i + 3] = 1.0f / (float)max(d.w, 1);
    }
}

__global__ void k_scatter(const int* __restrict__ ei) {
    int e = blockIdx.x * blockDim.x + threadIdx.x;
    if (e < NE) {
        int dst = ei[NE + e];
        int p = atomicAdd(&g_fill[dst], 1);
        g_col[p] = ei[e];
    }
}

// ---------------- weight -> fp16 mma-fragment layout ---------------------------
__global__ void k_cvt_w(const float* __restrict__ Wl0, const float* __restrict__ Wr0,
                        const float* __restrict__ Wl1, const float* __restrict__ Wr1) {
    int idx = blockIdx.x * blockDim.x + threadIdx.x;
    if (idx >= 3 * 4096) return;
    int lane = idx & 31;
    int n8   = (idx >> 5) & 15;
    int ks   = (idx >> 9) & 7;
    int m    = idx >> 12;
    int n  = n8 * 8 + (lane >> 2);
    int k0 = ks * 16 + (lane & 3) * 2;
    auto w = [&](int k) -> float {
        if (m == 0) return Wl0[k * 128 + n];
        if (m == 1) return Wr0[k * 128 + n];
        return (n < 64) ? Wl1[k * 64 + n] : Wr1[k * 64 + (n - 64)];
    };
    g_Bq[idx] = make_uint2(packh2(w(k0), w(k0 + 1)), packh2(w(k0 + 8), w(k0 + 9)));
}

// ---------------- fp16 HMMA GEMM core -------------------------------------------
#define LDAB 136
#define TILE_B (128 * LDAB * 2)          // 34816 bytes (one fp16 tile)

static __device__ __forceinline__ void gemm_fp16(float (&acc)[4][4][4],
                                                 const uint32_t aOff[4],
                                                 const uint2* __restrict__ Bq,
                                                 int wn, int lane) {
#pragma unroll
    for (int mf = 0; mf < 4; mf++)
#pragma unroll
        for (int nf = 0; nf < 4; nf++)
#pragma unroll
            for (int q = 0; q < 4; q++) acc[mf][nf][q] = 0.f;
#pragma unroll
    for (int ks = 0; ks < 8; ks++) {
        const uint32_t kb = ks * 32;       // 16 halves = 32 bytes
        const int fibase = (ks * 16 + wn * 4) * 32 + lane;
        uint2 bq[4];
#pragma unroll
        for (int nf = 0; nf < 4; nf++) bq[nf] = Bq[fibase + nf * 32];
        uint32_t a[4][4];
#pragma unroll
        for (int mf = 0; mf < 4; mf++) ldm_x4(a[mf], aOff[mf] + kb);
#pragma unroll
        for (int mf = 0; mf < 4; mf++)
#pragma unroll
            for (int nf = 0; nf < 4; nf++)
                mma16816h(acc[mf][nf], a[mf], bq[nf].x, bq[nf].y);
    }
}

// merged layer-0 GEMM: stage x->fp16 ONCE, two fp16 MMA passes.
// pass 1: Wl0^T -> Zl (fp16, ld 128). pass 2: Wr0^T -> Zr (fp32, ld 128).
__global__ __launch_bounds__(256, 2)
void k_mma0dual(const float* __restrict__ A,
                const uint2* __restrict__ Bq0, const uint2* __restrict__ Bq1,
                __half* __restrict__ Cl, float* __restrict__ Cr, int M) {
    extern __shared__ char smem[];
    const uint32_t sb = smem_u32(smem);
    const int tid = threadIdx.x, wid = tid >> 5, lane = tid & 31;
    const int rowBase = blockIdx.x * 128;

    // ---- stage A: fp32 -> fp16 (once) ----
#pragma unroll
    for (int i = 0; i < 8; i++) {
        int f = tid + i * 256;
        int r = f >> 4, c16 = f & 15;
        uint32_t off = (uint32_t)r * (LDAB * 2) + c16 * 16;
        int gr = rowBase + r;
        float4 v0 = make_float4(0.f, 0.f, 0.f, 0.f), v1 = v0;
        if (gr < M) {
            const float* ap = A + (size_t)gr * 128 + c16 * 8;
            v0 = *(const float4*)ap;
            v1 = *(const float4*)(ap + 4);
        }
        uint4 q;
        q.x = packh2(v0.x, v0.y);
        q.y = packh2(v0.z, v0.w);
        q.z = packh2(v1.x, v1.y);
        q.w = packh2(v1.z, v1.w);
        *(uint4*)(smem + off) = q;
    }
    __syncthreads();

    const int wm = wid & 1, wn = wid >> 1;
    const int aRow = wm * 64 + (lane & 7) + ((lane >> 3) & 1) * 8;
    const int aCol = ((lane >> 4) & 1) * 8;
    uint32_t aOff[4];
#pragma unroll
    for (int mf = 0; mf < 4; mf++)
        aOff[mf] = sb + (uint32_t)(aRow + mf * 16) * (LDAB * 2) + (uint32_t)aCol * 2;

    const int quad = lane >> 2, pairc = (lane & 3) * 2;
    float acc[4][4][4];

    // pass 1: Zl (fp16 out)
    gemm_fp16(acc, aOff, Bq0, wn, lane);
#pragma unroll
    for (int mf = 0; mf < 4; mf++) {
        int r0 = rowBase + wm * 64 + mf * 16 + quad;
#pragma unroll
        for (int nf = 0; nf < 4; nf++) {
            int c0 = wn * 32 + nf * 8 + pairc;
            if (r0 < M)
                *(uint32_t*)(Cl + (size_t)r0 * 128 + c0) = packh2(acc[mf][nf][0], acc[mf][nf][1]);
            if (r0 + 8 < M)
                *(uint32_t*)(Cl + (size_t)(r0 + 8) * 128 + c0) = packh2(acc[mf][nf][2], acc[mf][nf][3]);
        }
    }

    // pass 2: Zr (fp32 out)
    gemm_fp16(acc, aOff, Bq1, wn, lane);
#pragma unroll
    for (int mf = 0; mf < 4; mf++) {
        int r0 = rowBase + wm * 64 + mf * 16 + quad;
#pragma unroll
        for (int nf = 0; nf < 4; nf++) {
            int c0 = wn * 32 + nf * 8 + pairc;
            if (r0 < M)
                *(float2*)(Cr + (size_t)r0 * 128 + c0) = make_float2(acc[mf][nf][0], acc[mf][nf][1]);
            if (r0 + 8 < M)
                *(float2*)(Cr + (size_t)(r0 + 8) * 128 + c0) = make_float2(acc[mf][nf][2], acc[mf][nf][3]);
        }
    }
}

// layer-1 GEMM: single-pass fp16 (A = h fp16, B = [Wl1|Wr1] fp16).
// Split out: Y1l bf16 (ld 64) + Y1r fp32 (ld 64).
__global__ __launch_bounds__(256, 2)
void k_mma1(const __half* __restrict__ A, const uint2* __restrict__ Bq,
            __nv_bfloat16* __restrict__ Cl, float* __restrict__ Cr, int M) {
    extern __shared__ char smem[];
    const uint32_t sb = smem_u32(smem);
    const int tid = threadIdx.x, wid = tid >> 5, lane = tid & 31;
    const int rowBase = blockIdx.x * 128;

#pragma unroll
    for (int i = 0; i < 8; i++) {
        int f = tid + i * 256;
        int r = f >> 4, c16 = f & 15;
        uint32_t off = (uint32_t)r * (LDAB * 2) + c16 * 16;
        int gr = rowBase + r;
        uint4 v = make_uint4(0, 0, 0, 0);
        if (gr < M) v = *(const uint4*)(A + (size_t)gr * 128 + c16 * 8);
        *(uint4*)(smem + off) = v;
    }
    __syncthreads();

    const int wm = wid & 1, wn = wid >> 1;
    const int aRow = wm * 64 + (lane & 7) + ((lane >> 3) & 1) * 8;
    const int aCol = ((lane >> 4) & 1) * 8;
    uint32_t aOff[4];
#pragma unroll
    for (int mf = 0; mf < 4; mf++)
        aOff[mf] = sb + (uint32_t)(aRow + mf * 16) * (LDAB * 2) + (uint32_t)aCol * 2;

    float acc[4][4][4];
    gemm_fp16(acc, aOff, Bq, wn, lane);

    const int quad = lane >> 2, pairc = (lane & 3) * 2;
#pragma unroll
    for (int mf = 0; mf < 4; mf++) {
        int r0 = rowBase + wm * 64 + mf * 16 + quad;
#pragma unroll
        for (int nf = 0; nf < 4; nf++) {
            int c0 = wn * 32 + nf * 8 + pairc;
            if (c0 < 64) {
                if (r0 < M)
                    *(uint32_t*)(Cl + (size_t)r0 * 64 + c0) = packbf2(acc[mf][nf][0], acc[mf][nf][1]);
                if (r0 + 8 < M)
                    *(uint32_t*)(Cl + (size_t)(r0 + 8) * 64 + c0) = packbf2(acc[mf][nf][2], acc[mf][nf][3]);
            } else {
                int c1 = c0 - 64;
                if (r0 < M)
                    *(float2*)(Cr + (size_t)r0 * 64 + c1) = make_float2(acc[mf][nf][0], acc[mf][nf][1]);
                if (r0 + 8 < M)
                    *(float2*)(Cr + (size_t)(r0 + 8) * 64 + c1) = make_float2(acc[mf][nf][2], acc[mf][nf][3]);
            }
        }
    }
}

// ---------------- aggregation epilogues ------------------------------------------
// layer 0: h = relu( inv*sum_j fp16(Zl[j]) + Zr[i] + b0 ), emit fp16
__global__ void k_agg0(const float* __restrict__ b0) {
    int w = (blockIdx.x * blockDim.x + threadIdx.x) >> 5;
    int lane = threadIdx.x & 31;
    if (w >= NN) return;
    int s = g_rowptr[w], e = g_rowptr[w + 1];
    const uint2* Z = (const uint2*)g_Zl;      // 32 uint2 (256B) per row
    float4 acc = make_float4(0.f, 0.f, 0.f, 0.f);
    for (int p = s; p < e; p++) {
        int j = g_col[p];
        uint2 v = Z[(size_t)j * 32 + lane];
        float2 f01 = __half22float2(*reinterpret_cast<const __half2*>(&v.x));
        float2 f23 = __half22float2(*reinterpret_cast<const __half2*>(&v.y));
        acc.x += f01.x; acc.y += f01.y; acc.z += f23.x; acc.w += f23.y;
    }
    float inv = g_inv[w];
    float4 r = ((const float4*)g_Zr)[(size_t)w * 32 + lane];
    float4 bb = ((const float4*)b0)[lane];
    float o0 = fmaxf(fmaf(acc.x, inv, r.x + bb.x), 0.f);
    float o1 = fmaxf(fmaf(acc.y, inv, r.y + bb.y), 0.f);
    float o2 = fmaxf(fmaf(acc.z, inv, r.z + bb.z), 0.f);
    float o3 = fmaxf(fmaf(acc.w, inv, r.w + bb.w), 0.f);
    ((uint2*)g_h16)[(size_t)w * 32 + lane] = make_uint2(packh2(o0, o1), packh2(o2, o3));
}

// layer 1: h2 = inv*sum_j bf16(Y1l[j]) + Y1r[i] + b1 (fp32 accum, fp16 out)
__global__ void k_agg1(const float* __restrict__ b1) {
    int w = (blockIdx.x * blockDim.x + threadIdx.x) >> 5;
    int lane = threadIdx.x & 31;
    if (w >= NN) return;
    int s = g_rowptr[w], e = g_rowptr[w + 1];
    const uint32_t* Yl = (const uint32_t*)g_Y1l;   // 32 uint32 (128B) per row
    float2 acc = make_float2(0.f, 0.f);
    for (int p = s; p < e; p++) {
        int j = g_col[p];
        uint32_t v = Yl[(size_t)j * 32 + lane];
        float2 f = __bfloat1622float2(*reinterpret_cast<const __nv_bfloat162*>(&v));
        acc.x += f.x; acc.y += f.y;
    }
    float inv = g_inv[w];
    float2 r = ((const float2*)g_Y1r)[(size_t)w * 32 + lane];
    float2 bb = ((const float2*)b1)[lane];
    float ox = fmaf(acc.x, inv, r.x + bb.x);
    float oy = fmaf(acc.y, inv, r.y + bb.y);
    ((uint32_t*)g_h2)[(size_t)w * 32 + lane] = packh2(ox, oy);
}

// ---------------- edge scoring: 4 edges/warp, 8 lanes/edge ----------------------
__global__ void k_score(const int* __restrict__ pe, const int* __restrict__ ne,
                        float* __restrict__ out) {
    int gw = (blockIdx.x * blockDim.x + threadIdx.x) >> 5;   // warp id
    int lane = threadIdx.x & 31;
    int g = lane >> 3, l8 = lane & 7;
    int e = gw * 4 + g;                 // edge id in [0, 2*NEP); warps never straddle
    if (e >= 2 * NEP) return;
    int a, b;
    if (e < NEP) { a = pe[e]; b = pe[NEP + e]; }
    else         { int q = e - NEP; a = ne[q]; b = ne[NEP + q]; }
    const uint4* H = (const uint4*)g_h2;    // row = 8 uint4 (64 halves)
    uint4 ua = H[(size_t)a * 8 + l8];
    uint4 ub = H[(size_t)b * 8 + l8];
    float s;
    {
        float2 a0 = __half22float2(*reinterpret_cast<const __half2*>(&ua.x));
        float2 b0 = __half22float2(*reinterpret_cast<const __half2*>(&ub.x));
        float2 a1 = __half22float2(*reinterpret_cast<const __half2*>(&ua.y));
        float2 b1 = __half22float2(*reinterpret_cast<const __half2*>(&ub.y));
        float2 a2 = __half22float2(*reinterpret_cast<const __half2*>(&ua.z));
        float2 b2 = __half22float2(*reinterpret_cast<const __half2*>(&ub.z));
        float2 a3 = __half22float2(*reinterpret_cast<const __half2*>(&ua.w));
        float2 b3 = __half22float2(*reinterpret_cast<const __half2*>(&ub.w));
        s = a0.x * b0.x;
        s = fmaf(a0.y, b0.y, s);
        s = fmaf(a1.x, b1.x, s);
        s = fmaf(a1.y, b1.y, s);
        s = fmaf(a2.x, b2.x, s);
        s = fmaf(a2.y, b2.y, s);
        s = fmaf(a3.x, b3.x, s);
        s = fmaf(a3.y, b3.y, s);
    }
    s += __shfl_xor_sync(0xffffffffu, s, 4);
    s += __shfl_xor_sync(0xffffffffu, s, 2);
    s += __shfl_xor_sync(0xffffffffu, s, 1);
    if (l8 == 0) out[e] = s;
}

// ---------------- launcher -----------------------------------------------------
extern "C" void kernel_launch(void* const* d_in, const int* in_sizes, int n_in,
                              void* d_out, int out_size) {
    const float* x   = (const float*)d_in[0];
    const int*   ei  = (const int*)d_in[1];
    const int*   pe  = (const int*)d_in[2];
    const int*   ne  = (const int*)d_in[3];
    const float* Wl0 = (const float*)d_in[4];
    const float* b0  = (const float*)d_in[5];
    const float* Wr0 = (const float*)d_in[6];
    const float* Wl1 = (const float*)d_in[7];
    const float* b1  = (const float*)d_in[8];
    const float* Wr1 = (const float*)d_in[9];
    float* out = (float*)d_out;

    static cudaStream_t s1 = nullptr;
    static cudaEvent_t eF = nullptr, e1 = nullptr;
    if (s1 == nullptr) {
        cudaStreamCreateWithFlags(&s1, cudaStreamNonBlocking);
        cudaEventCreateWithFlags(&eF, cudaEventDisableTiming);
        cudaEventCreateWithFlags(&e1, cudaEventDisableTiming);
        cudaFuncSetAttribute(k_mma0dual, cudaFuncAttributeMaxDynamicSharedMemorySize, TILE_B);
        cudaFuncSetAttribute(k_mma1,     cudaFuncAttributeMaxDynamicSharedMemorySize, TILE_B);
    }

    __half *pZl, *pH16;
    __nv_bfloat16 *pY1l;
    float *pZr, *pY1r;
    uint2 *pBq;
    int *pDeg;
    cudaGetSymbolAddress((void**)&pZl,  g_Zl);
    cudaGetSymbolAddress((void**)&pZr,  g_Zr);
    cudaGetSymbolAddress((void**)&pH16, g_h16);
    cudaGetSymbolAddress((void**)&pY1l, g_Y1l);
    cudaGetSymbolAddress((void**)&pY1r, g_Y1r);
    cudaGetSymbolAddress((void**)&pBq,  g_Bq);
    cudaGetSymbolAddress((void**)&pDeg, g_deg);

    const int NB = (NN + 1023) / 1024;   // 98
    const int GX = (NN + 127) / 128;     // 782

    // fork: s1 branches off the main (captured) stream
    cudaEventRecord(eF, 0);
    cudaStreamWaitEvent(s1, eF, 0);

    // branch A (s1): weights -> merged fp16 layer-0 GEMM (A staged once, 2 passes)
    k_cvt_w<<<48, 256, 0, s1>>>(Wl0, Wr0, Wl1, Wr1);
    k_mma0dual<<<GX, 256, TILE_B, s1>>>(x, pBq, pBq + 4096, pZl, pZr, NN);

    // branch B (main stream): CSR build
    cudaMemsetAsync(pDeg, 0, NN * sizeof(int), 0);
    k_count<<<(NE + 255) / 256, 256>>>(ei);
    k_scan1<<<NB, 256>>>();
    k_scan2<<<1, 128>>>(NB);
    k_scan3<<<NB, 256>>>();
    k_scatter<<<(NE + 255) / 256, 256>>>(ei);

    // join
    cudaEventRecord(e1, s1);
    cudaStreamWaitEvent(0, e1, 0);

    // layer 0 aggregate (fp16 h), layer 1 fp16 GEMM, layer-1 aggregate, scores
    k_agg0<<<(NN * 32 + 255) / 256, 256>>>(b0);
    k_mma1<<<GX, 256, TILE_B>>>(pH16, pBq + 8192, pY1l, pY1r, NN);
    k_agg1<<<(NN * 32 + 255) / 256, 256>>>(b1);
    // 4 edges per warp: 2*NEP/4 = 250K warps -> 31250 blocks of 256 threads
    k_score<<<(2 * NEP / 4 * 32) / 256, 256>>>(pe, ne, out);
}

// round 16
// speedup vs baseline: 1.2824x; 1.0090x over previous
#include <cuda_runtime.h>
#include <cuda_bf16.h>
#include <cuda_fp16.h>
#include <cstdint>

#define NN 100000
#define NE 1600000
#define NEP 500000

// ---------------- scratch (device globals) ------------------------------------
__device__ int   g_deg[NN];
__device__ int   g_rowptr[NN + 1];
__device__ int   g_fill[NN];
__device__ float g_inv[NN];
__device__ int   g_col[NE];
__device__ int   g_bsum[128];
__device__ __half g_Zl[(size_t)NN * 128];         // x @ W_l0  (fp16 — gathered 16x)
__device__ __half g_base0[(size_t)NN * 128];      // x @ W_r0 + b0 (fp16 — read once)
__device__ __half g_h16[(size_t)NN * 128];        // layer-0 output (fp16)
__device__ __nv_bfloat16 g_Y1l[(size_t)NN * 64];  // h @ W_l1 (bf16 — gathered 16x)
__device__ __half g_base1[(size_t)NN * 64];       // h @ W_r1 + b1 (fp16 — read once)
__device__ __half g_h2[(size_t)NN * 64];          // layer-1 output (fp16, 128B rows)
// B fragments (fp16), per-lane mma layout: m=0 Wl0^T, m=1 Wr0^T, m=2 [Wl1|Wr1]^T
__device__ uint2 g_Bq[3 * 4096];

// ---------------- helpers -------------------------------------------------------
static __device__ __forceinline__ uint32_t smem_u32(const void* p) {
    uint32_t a;
    asm("{ .reg .u64 t; cvta.to.shared.u64 t, %1; cvt.u32.u64 %0, t; }" : "=r"(a) : "l"(p));
    return a;
}

static __device__ __forceinline__ void ldm_x4(uint32_t r[4], uint32_t addr) {
    asm volatile("ldmatrix.sync.aligned.m8n8.x4.shared.b16 {%0,%1,%2,%3}, [%4];"
        : "=r"(r[0]), "=r"(r[1]), "=r"(r[2]), "=r"(r[3]) : "r"(addr));
}

static __device__ __forceinline__ void mma16816h(float c[4], const uint32_t a[4],
                                                 const uint32_t b0, const uint32_t b1) {
    asm volatile("mma.sync.aligned.m16n8k16.row.col.f32.f16.f16.f32 "
        "{%0,%1,%2,%3}, {%4,%5,%6,%7}, {%8,%9}, {%0,%1,%2,%3};"
        : "+f"(c[0]), "+f"(c[1]), "+f"(c[2]), "+f"(c[3])
        : "r"(a[0]), "r"(a[1]), "r"(a[2]), "r"(a[3]), "r"(b0), "r"(b1));
}

static __device__ __forceinline__ uint32_t packbf2(float a, float b) {
    __nv_bfloat162 p = __float22bfloat162_rn(make_float2(a, b));
    return *reinterpret_cast<uint32_t*>(&p);
}

static __device__ __forceinline__ uint32_t packh2(float a, float b) {
    __half2 p = __floats2half2_rn(a, b);
    return *reinterpret_cast<uint32_t*>(&p);
}

// ---------------- CSR build ---------------------------------------------------
__global__ void k_count(const int* __restrict__ ei) {
    int e = blockIdx.x * blockDim.x + threadIdx.x;
    if (e < NE) atomicAdd(&g_deg[ei[NE + e]], 1);
}

__global__ void k_scan1() {
    int t = threadIdx.x, b = blockIdx.x;
    int i4 = b * 256 + t;
    int s = 0;
    if (i4 < NN / 4) {
        int4 d = ((const int4*)g_deg)[i4];
        s = d.x + d.y + d.z + d.w;
    }
    for (int o = 16; o; o >>= 1) s += __shfl_xor_sync(0xffffffffu, s, o);
    __shared__ int ws[8];
    if ((t & 31) == 0) ws[t >> 5] = s;
    __syncthreads();
    if (t == 0) {
        int tot = 0;
#pragma unroll
        for (int w = 0; w < 8; w++) tot += ws[w];
        g_bsum[b] = tot;
    }
}

// fused: per-block base from g_bsum (reduce over [0, blockIdx.x)), then row offsets
__global__ void k_scan3() {
    int t = threadIdx.x, b = blockIdx.x;
    int lane = t & 31, wid = t >> 5;

    // ---- compute sBase = sum(g_bsum[0..b)) ----
    __shared__ int ssum[8], sBaseSh;
    int part = (t < b) ? g_bsum[t] : 0;      // b <= 97 < 256
#pragma unroll
    for (int o = 16; o; o >>= 1) part += __shfl_xor_sync(0xffffffffu, part, o);
    if (lane == 0) ssum[wid] = part;
    __syncthreads();
    if (t == 0) {
        int r = 0;
#pragma unroll
        for (int w = 0; w < 8; w++) r += ssum[w];
        sBaseSh = r;
        if (b == 0) g_rowptr[NN] = NE;
    }
    __syncthreads();
    const int sBase = sBaseSh;

    int i4 = b * 256 + t;
    int4 d = make_int4(0, 0, 0, 0);
    bool act = (i4 < NN / 4);
    if (act) d = ((const int4*)g_deg)[i4];
    int e0 = 0, e1 = d.x, e2 = d.x + d.y, e3 = d.x + d.y + d.z;
    int tsum = e3 + d.w;
    int v = tsum;
#pragma unroll
    for (int o = 1; o < 32; o <<= 1) {
        int u = __shfl_up_sync(0xffffffffu, v, o);
        if (lane >= o) v += u;
    }
    __shared__ int wsum[8], woff[8];
    if (lane == 31) wsum[wid] = v;
    __syncthreads();
    if (t == 0) {
        int r = 0;
#pragma unroll
        for (int w = 0; w < 8; w++) { int tmp = wsum[w]; woff[w] = r; r += tmp; }
    }
    __syncthreads();
    if (act) {
        int base = sBase + woff[wid] + (v - tsum);
        int i = i4 * 4;
        g_rowptr[i + 0] = base + e0;  g_fill[i + 0] = base + e0;
        g_rowptr[i + 1] = base + e1;  g_fill[i + 1] = base + e1;
        g_rowptr[i + 2] = base + e2;  g_fill[i + 2] = base + e2;
        g_rowptr[i + 3] = base + e3;  g_fill[i + 3] = base + e3;
        g_inv[i + 0] = 1.0f / (float)max(d.x, 1);
        g_inv[i + 1] = 1.0f / (float)max(d.y, 1);
        g_inv[i + 2] = 1.0f / (float)max(d.z, 1);
        g_inv[i + 3] = 1.0f / (float)max(d.w, 1);
    }
}

__global__ void k_scatter(const int* __restrict__ ei) {
    int e = blockIdx.x * blockDim.x + threadIdx.x;
    if (e < NE) {
        int dst = ei[NE + e];
        int p = atomicAdd(&g_fill[dst], 1);
        g_col[p] = ei[e];
    }
}

// ---------------- weight -> fp16 mma-fragment layout ---------------------------
__global__ void k_cvt_w(const float* __restrict__ Wl0, const float* __restrict__ Wr0,
                        const float* __restrict__ Wl1, const float* __restrict__ Wr1) {
    int idx = blockIdx.x * blockDim.x + threadIdx.x;
    if (idx >= 3 * 4096) return;
    int lane = idx & 31;
    int n8   = (idx >> 5) & 15;
    int ks   = (idx >> 9) & 7;
    int m    = idx >> 12;
    int n  = n8 * 8 + (lane >> 2);
    int k0 = ks * 16 + (lane & 3) * 2;
    auto w = [&](int k) -> float {
        if (m == 0) return Wl0[k * 128 + n];
        if (m == 1) return Wr0[k * 128 + n];
        return (n < 64) ? Wl1[k * 64 + n] : Wr1[k * 64 + (n - 64)];
    };
    g_Bq[idx] = make_uint2(packh2(w(k0), w(k0 + 1)), packh2(w(k0 + 8), w(k0 + 9)));
}

// ---------------- fp16 HMMA GEMM core -------------------------------------------
#define LDAB 136
#define TILE_B (128 * LDAB * 2)          // 34816 bytes (one fp16 tile)

static __device__ __forceinline__ void gemm_fp16(float (&acc)[4][4][4],
                                                 const uint32_t aOff[4],
                                                 const uint2* __restrict__ Bq,
                                                 int wn, int lane) {
#pragma unroll
    for (int mf = 0; mf < 4; mf++)
#pragma unroll
        for (int nf = 0; nf < 4; nf++)
#pragma unroll
            for (int q = 0; q < 4; q++) acc[mf][nf][q] = 0.f;
#pragma unroll
    for (int ks = 0; ks < 8; ks++) {
        const uint32_t kb = ks * 32;       // 16 halves = 32 bytes
        const int fibase = (ks * 16 + wn * 4) * 32 + lane;
        uint2 bq[4];
#pragma unroll
        for (int nf = 0; nf < 4; nf++) bq[nf] = Bq[fibase + nf * 32];
        uint32_t a[4][4];
#pragma unroll
        for (int mf = 0; mf < 4; mf++) ldm_x4(a[mf], aOff[mf] + kb);
#pragma unroll
        for (int mf = 0; mf < 4; mf++)
#pragma unroll
            for (int nf = 0; nf < 4; nf++)
                mma16816h(acc[mf][nf], a[mf], bq[nf].x, bq[nf].y);
    }
}

// merged layer-0 GEMM: stage x->fp16 ONCE, two fp16 MMA passes.
// pass 1: Wl0^T -> Zl (fp16). pass 2: Wr0^T + b0 -> base0 (fp16).
__global__ __launch_bounds__(256, 2)
void k_mma0dual(const float* __restrict__ A,
                const uint2* __restrict__ Bq0, const uint2* __restrict__ Bq1,
                const float* __restrict__ b0,
                __half* __restrict__ Cl, __half* __restrict__ Cb, int M) {
    extern __shared__ char smem[];
    const uint32_t sb = smem_u32(smem);
    const int tid = threadIdx.x, wid = tid >> 5, lane = tid & 31;
    const int rowBase = blockIdx.x * 128;

    // ---- stage A: fp32 -> fp16 (once) ----
#pragma unroll
    for (int i = 0; i < 8; i++) {
        int f = tid + i * 256;
        int r = f >> 4, c16 = f & 15;
        uint32_t off = (uint32_t)r * (LDAB * 2) + c16 * 16;
        int gr = rowBase + r;
        float4 v0 = make_float4(0.f, 0.f, 0.f, 0.f), v1 = v0;
        if (gr < M) {
            const float* ap = A + (size_t)gr * 128 + c16 * 8;
            v0 = *(const float4*)ap;
            v1 = *(const float4*)(ap + 4);
        }
        uint4 q;
        q.x = packh2(v0.x, v0.y);
        q.y = packh2(v0.z, v0.w);
        q.z = packh2(v1.x, v1.y);
        q.w = packh2(v1.z, v1.w);
        *(uint4*)(smem + off) = q;
    }
    __syncthreads();

    const int wm = wid & 1, wn = wid >> 1;
    const int aRow = wm * 64 + (lane & 7) + ((lane >> 3) & 1) * 8;
    const int aCol = ((lane >> 4) & 1) * 8;
    uint32_t aOff[4];
#pragma unroll
    for (int mf = 0; mf < 4; mf++)
        aOff[mf] = sb + (uint32_t)(aRow + mf * 16) * (LDAB * 2) + (uint32_t)aCol * 2;

    const int quad = lane >> 2, pairc = (lane & 3) * 2;
    float acc[4][4][4];

    // pass 1: Zl (fp16 out)
    gemm_fp16(acc, aOff, Bq0, wn, lane);
#pragma unroll
    for (int mf = 0; mf < 4; mf++) {
        int r0 = rowBase + wm * 64 + mf * 16 + quad;
#pragma unroll
        for (int nf = 0; nf < 4; nf++) {
            int c0 = wn * 32 + nf * 8 + pairc;
            if (r0 < M)
                *(uint32_t*)(Cl + (size_t)r0 * 128 + c0) = packh2(acc[mf][nf][0], acc[mf][nf][1]);
            if (r0 + 8 < M)
                *(uint32_t*)(Cl + (size_t)(r0 + 8) * 128 + c0) = packh2(acc[mf][nf][2], acc[mf][nf][3]);
        }
    }

    // pass 2: base0 = Zr + b0 (fp16 out)
    gemm_fp16(acc, aOff, Bq1, wn, lane);
#pragma unroll
    for (int mf = 0; mf < 4; mf++) {
        int r0 = rowBase + wm * 64 + mf * 16 + quad;
#pragma unroll
        for (int nf = 0; nf < 4; nf++) {
            int c0 = wn * 32 + nf * 8 + pairc;
            float2 bb = *(const float2*)(b0 + c0);
            uint32_t lo = packh2(acc[mf][nf][0] + bb.x, acc[mf][nf][1] + bb.y);
            uint32_t hi = packh2(acc[mf][nf][2] + bb.x, acc[mf][nf][3] + bb.y);
            if (r0 < M)
                *(uint32_t*)(Cb + (size_t)r0 * 128 + c0) = lo;
            if (r0 + 8 < M)
                *(uint32_t*)(Cb + (size_t)(r0 + 8) * 128 + c0) = hi;
        }
    }
}

// layer-1 GEMM: single-pass fp16. Split out: Y1l bf16 (ld 64) + base1 fp16 (ld 64,
// with b1 folded in).
__global__ __launch_bounds__(256, 2)
void k_mma1(const __half* __restrict__ A, const uint2* __restrict__ Bq,
            const float* __restrict__ b1,
            __nv_bfloat16* __restrict__ Cl, __half* __restrict__ Cb, int M) {
    extern __shared__ char smem[];
    const uint32_t sb = smem_u32(smem);
    const int tid = threadIdx.x, wid = tid >> 5, lane = tid & 31;
    const int rowBase = blockIdx.x * 128;

#pragma unroll
    for (int i = 0; i < 8; i++) {
        int f = tid + i * 256;
        int r = f >> 4, c16 = f & 15;
        uint32_t off = (uint32_t)r * (LDAB * 2) + c16 * 16;
        int gr = rowBase + r;
        uint4 v = make_uint4(0, 0, 0, 0);
        if (gr < M) v = *(const uint4*)(A + (size_t)gr * 128 + c16 * 8);
        *(uint4*)(smem + off) = v;
    }
    __syncthreads();

    const int wm = wid & 1, wn = wid >> 1;
    const int aRow = wm * 64 + (lane & 7) + ((lane >> 3) & 1) * 8;
    const int aCol = ((lane >> 4) & 1) * 8;
    uint32_t aOff[4];
#pragma unroll
    for (int mf = 0; mf < 4; mf++)
        aOff[mf] = sb + (uint32_t)(aRow + mf * 16) * (LDAB * 2) + (uint32_t)aCol * 2;

    float acc[4][4][4];
    gemm_fp16(acc, aOff, Bq, wn, lane);

    const int quad = lane >> 2, pairc = (lane & 3) * 2;
#pragma unroll
    for (int mf = 0; mf < 4; mf++) {
        int r0 = rowBase + wm * 64 + mf * 16 + quad;
#pragma unroll
        for (int nf = 0; nf < 4; nf++) {
            int c0 = wn * 32 + nf * 8 + pairc;
            if (c0 < 64) {
                if (r0 < M)
                    *(uint32_t*)(Cl + (size_t)r0 * 64 + c0) = packbf2(acc[mf][nf][0], acc[mf][nf][1]);
                if (r0 + 8 < M)
                    *(uint32_t*)(Cl + (size_t)(r0 + 8) * 64 + c0) = packbf2(acc[mf][nf][2], acc[mf][nf][3]);
            } else {
                int c1 = c0 - 64;
                float2 bb = *(const float2*)(b1 + c1);
                uint32_t lo = packh2(acc[mf][nf][0] + bb.x, acc[mf][nf][1] + bb.y);
                uint32_t hi = packh2(acc[mf][nf][2] + bb.x, acc[mf][nf][3] + bb.y);
                if (r0 < M)
                    *(uint32_t*)(Cb + (size_t)r0 * 64 + c1) = lo;
                if (r0 + 8 < M)
                    *(uint32_t*)(Cb + (size_t)(r0 + 8) * 64 + c1) = hi;
            }
        }
    }
}

// ---------------- aggregation epilogues ------------------------------------------
// layer 0: h = relu( inv*sum_j fp16(Zl[j]) + base0[i] ), emit fp16
__global__ void k_agg0() {
    int w = (blockIdx.x * blockDim.x + threadIdx.x) >> 5;
    int lane = threadIdx.x & 31;
    if (w >= NN) return;
    int s = g_rowptr[w], e = g_rowptr[w + 1];
    const uint2* Z = (const uint2*)g_Zl;      // 32 uint2 (256B) per row
    float4 acc = make_float4(0.f, 0.f, 0.f, 0.f);
    for (int p = s; p < e; p++) {
        int j = g_col[p];
        uint2 v = Z[(size_t)j * 32 + lane];
        float2 f01 = __half22float2(*reinterpret_cast<const __half2*>(&v.x));
        float2 f23 = __half22float2(*reinterpret_cast<const __half2*>(&v.y));
        acc.x += f01.x; acc.y += f01.y; acc.z += f23.x; acc.w += f23.y;
    }
    float inv = g_inv[w];
    uint2 bv = ((const uint2*)g_base0)[(size_t)w * 32 + lane];
    float2 r01 = __half22float2(*reinterpret_cast<const __half2*>(&bv.x));
    float2 r23 = __half22float2(*reinterpret_cast<const __half2*>(&bv.y));
    float o0 = fmaxf(fmaf(acc.x, inv, r01.x), 0.f);
    float o1 = fmaxf(fmaf(acc.y, inv, r01.y), 0.f);
    float o2 = fmaxf(fmaf(acc.z, inv, r23.x), 0.f);
    float o3 = fmaxf(fmaf(acc.w, inv, r23.y), 0.f);
    ((uint2*)g_h16)[(size_t)w * 32 + lane] = make_uint2(packh2(o0, o1), packh2(o2, o3));
}

// layer 1: h2 = inv*sum_j bf16(Y1l[j]) + base1[i] (fp32 accum, fp16 out)
__global__ void k_agg1() {
    int w = (blockIdx.x * blockDim.x + threadIdx.x) >> 5;
    int lane = threadIdx.x & 31;
    if (w >= NN) return;
    int s = g_rowptr[w], e = g_rowptr[w + 1];
    const uint32_t* Yl = (const uint32_t*)g_Y1l;   // 32 uint32 (128B) per row
    float2 acc = make_float2(0.f, 0.f);
    for (int p = s; p < e; p++) {
        int j = g_col[p];
        uint32_t v = Yl[(size_t)j * 32 + lane];
        float2 f = __bfloat1622float2(*reinterpret_cast<const __nv_bfloat162*>(&v));
        acc.x += f.x; acc.y += f.y;
    }
    float inv = g_inv[w];
    uint32_t rv = ((const uint32_t*)g_base1)[(size_t)w * 32 + lane];
    float2 r = __half22float2(*reinterpret_cast<const __half2*>(&rv));
    float ox = fmaf(acc.x, inv, r.x);
    float oy = fmaf(acc.y, inv, r.y);
    ((uint32_t*)g_h2)[(size_t)w * 32 + lane] = packh2(ox, oy);
}

// ---------------- edge scoring: 4 edges/warp, 8 lanes/edge ----------------------
__global__ void k_score(const int* __restrict__ pe, const int* __restrict__ ne,
                        float* __restrict__ out) {
    int gw = (blockIdx.x * blockDim.x + threadIdx.x) >> 5;   // warp id
    int lane = threadIdx.x & 31;
    int g = lane >> 3, l8 = lane & 7;
    int e = gw * 4 + g;                 // edge id in [0, 2*NEP); warps never straddle
    if (e >= 2 * NEP) return;
    int a, b;
    if (e < NEP) { a = pe[e]; b = pe[NEP + e]; }
    else         { int q = e - NEP; a = ne[q]; b = ne[NEP + q]; }
    const uint4* H = (const uint4*)g_h2;    // row = 8 uint4 (64 halves)
    uint4 ua = H[(size_t)a * 8 + l8];
    uint4 ub = H[(size_t)b * 8 + l8];
    float s;
    {
        float2 a0 = __half22float2(*reinterpret_cast<const __half2*>(&ua.x));
        float2 b0 = __half22float2(*reinterpret_cast<const __half2*>(&ub.x));
        float2 a1 = __half22float2(*reinterpret_cast<const __half2*>(&ua.y));
        float2 b1 = __half22float2(*reinterpret_cast<const __half2*>(&ub.y));
        float2 a2 = __half22float2(*reinterpret_cast<const __half2*>(&ua.z));
        float2 b2 = __half22float2(*reinterpret_cast<const __half2*>(&ub.z));
        float2 a3 = __half22float2(*reinterpret_cast<const __half2*>(&ua.w));
        float2 b3 = __half22float2(*reinterpret_cast<const __half2*>(&ub.w));
        s = a0.x * b0.x;
        s = fmaf(a0.y, b0.y, s);
        s = fmaf(a1.x, b1.x, s);
        s = fmaf(a1.y, b1.y, s);
        s = fmaf(a2.x, b2.x, s);
        s = fmaf(a2.y, b2.y, s);
        s = fmaf(a3.x, b3.x, s);
        s = fmaf(a3.y, b3.y, s);
    }
    s += __shfl_xor_sync(0xffffffffu, s, 4);
    s += __shfl_xor_sync(0xffffffffu, s, 2);
    s += __shfl_xor_sync(0xffffffffu, s, 1);
    if (l8 == 0) out[e] = s;
}

// ---------------- launcher -----------------------------------------------------
extern "C" void kernel_launch(void* const* d_in, const int* in_sizes, int n_in,
                              void* d_out, int out_size) {
    const float* x   = (const float*)d_in[0];
    const int*   ei  = (const int*)d_in[1];
    const int*   pe  = (const int*)d_in[2];
    const int*   ne  = (const int*)d_in[3];
    const float* Wl0 = (const float*)d_in[4];
    const float* b0  = (const float*)d_in[5];
    const float* Wr0 = (const float*)d_in[6];
    const float* Wl1 = (const float*)d_in[7];
    const float* b1  = (const float*)d_in[8];
    const float* Wr1 = (const float*)d_in[9];
    float* out = (float*)d_out;

    static cudaStream_t s1 = nullptr;
    static cudaEvent_t eF = nullptr, e1 = nullptr;
    if (s1 == nullptr) {
        cudaStreamCreateWithFlags(&s1, cudaStreamNonBlocking);
        cudaEventCreateWithFlags(&eF, cudaEventDisableTiming);
        cudaEventCreateWithFlags(&e1, cudaEventDisableTiming);
        cudaFuncSetAttribute(k_mma0dual, cudaFuncAttributeMaxDynamicSharedMemorySize, TILE_B);
        cudaFuncSetAttribute(k_mma1,     cudaFuncAttributeMaxDynamicSharedMemorySize, TILE_B);
    }

    __half *pZl, *pB0, *pH16, *pB1;
    __nv_bfloat16 *pY1l;
    uint2 *pBq;
    int *pDeg;
    cudaGetSymbolAddress((void**)&pZl,  g_Zl);
    cudaGetSymbolAddress((void**)&pB0,  g_base0);
    cudaGetSymbolAddress((void**)&pH16, g_h16);
    cudaGetSymbolAddress((void**)&pY1l, g_Y1l);
    cudaGetSymbolAddress((void**)&pB1,  g_base1);
    cudaGetSymbolAddress((void**)&pBq,  g_Bq);
    cudaGetSymbolAddress((void**)&pDeg, g_deg);

    const int NB = (NN + 1023) / 1024;   // 98
    const int GX = (NN + 127) / 128;     // 782

    // fork: s1 branches off the main (captured) stream
    cudaEventRecord(eF, 0);
    cudaStreamWaitEvent(s1, eF, 0);

    // branch A (s1): weights -> merged fp16 layer-0 GEMM (b0 folded into base0)
    k_cvt_w<<<48, 256, 0, s1>>>(Wl0, Wr0, Wl1, Wr1);
    k_mma0dual<<<GX, 256, TILE_B, s1>>>(x, pBq, pBq + 4096, b0, pZl, pB0, NN);

    // branch B (main stream): CSR build (scan2 fused into scan3)
    cudaMemsetAsync(pDeg, 0, NN * sizeof(int), 0);
    k_count<<<(NE + 255) / 256, 256>>>(ei);
    k_scan1<<<NB, 256>>>();
    k_scan3<<<NB, 256>>>();
    k_scatter<<<(NE + 255) / 256, 256>>>(ei);

    // join
    cudaEventRecord(e1, s1);
    cudaStreamWaitEvent(0, e1, 0);

    // layer 0 aggregate, layer 1 fp16 GEMM (b1 folded), layer-1 aggregate, scores
    k_agg0<<<(NN * 32 + 255) / 256, 256>>>();
    k_mma1<<<GX, 256, TILE_B>>>(pH16, pBq + 8192, b1, pY1l, pB1, NN);
    k_agg1<<<(NN * 32 + 255) / 256, 256>>>();
    // 4 edges per warp: 2*NEP/4 = 250K warps -> 31250 blocks of 256 threads
    k_score<<<(2 * NEP / 4 * 32) / 256, 256>>>(pe, ne, out);
}